// round 1
// baseline (speedup 1.0000x reference)
#include <cuda_runtime.h>
#include <cuda_bf16.h>

#define S_TOT 2112          // 64 mem + 2048 tokens
#define T_LEN 2048
#define MEMN  64
#define DIM   768
#define HID   3072
#define NHEAD 12
#define HD    64
#define NLAYER 4

// ---------------- scratch (device globals; no allocation allowed) ----------
__device__ __align__(16) float g_X [S_TOT * DIM];
__device__ __align__(16) float g_N [S_TOT * DIM];
__device__ __align__(16) float g_Q [S_TOT * DIM];
__device__ __align__(16) float g_K [S_TOT * DIM];
__device__ __align__(16) float g_V [S_TOT * DIM];
__device__ __align__(16) float g_A [S_TOT * DIM];
__device__ __align__(16) float g_F [S_TOT * HID];

// ---------------- embedding ------------------------------------------------
__global__ void embed_kernel(const int* __restrict__ tokens,
                             const float* __restrict__ emb,
                             const float* __restrict__ pos,
                             const float* __restrict__ mem,
                             float* __restrict__ X)
{
    int idx = blockIdx.x * 256 + threadIdx.x;
    if (idx >= S_TOT * DIM) return;
    int s = idx / DIM;
    int d = idx - s * DIM;
    if (s < MEMN) {
        X[idx] = mem[s * DIM + d];
    } else {
        int t = s - MEMN;
        X[idx] = emb[tokens[t] * DIM + d] + pos[t * DIM + d];
    }
}

// ---------------- layernorm (one row per block, 256 threads) ---------------
__global__ void ln_kernel(const float* __restrict__ X,
                          const float* __restrict__ g,
                          const float* __restrict__ bt,
                          float* __restrict__ out,
                          int in_off)
{
    int row = blockIdx.x + in_off;
    const float* x = X + (size_t)row * DIM;
    int t = threadIdx.x;
    float v0 = x[t], v1 = x[t + 256], v2 = x[t + 512];
    float s = v0 + v1 + v2;
    float q = v0 * v0 + v1 * v1 + v2 * v2;
#pragma unroll
    for (int off = 16; off; off >>= 1) {
        s += __shfl_xor_sync(0xffffffffu, s, off);
        q += __shfl_xor_sync(0xffffffffu, q, off);
    }
    __shared__ float rs[8], rq[8];
    __shared__ float mean_sh, inv_sh;
    int w = t >> 5;
    if ((t & 31) == 0) { rs[w] = s; rq[w] = q; }
    __syncthreads();
    if (t == 0) {
        float S = 0.f, Q = 0.f;
#pragma unroll
        for (int i = 0; i < 8; i++) { S += rs[i]; Q += rq[i]; }
        float mean = S * (1.0f / DIM);
        float var  = Q * (1.0f / DIM) - mean * mean;
        mean_sh = mean;
        inv_sh  = rsqrtf(var + 1e-5f);
    }
    __syncthreads();
    float mean = mean_sh, inv = inv_sh;
    float* o = out + (size_t)blockIdx.x * DIM;
    o[t]       = (v0 - mean) * inv * g[t]       + bt[t];
    o[t + 256] = (v1 - mean) * inv * g[t + 256] + bt[t + 256];
    o[t + 512] = (v2 - mean) * inv * g[t + 512] + bt[t + 512];
}

// ---------------- gelu (tanh approximation, matches jax approximate=True) --
__device__ __forceinline__ float gelu_tanh(float x)
{
    const float c = 0.7978845608028654f; // sqrt(2/pi)
    float u = c * (x + 0.044715f * x * x * x);
    return 0.5f * x * (1.0f + tanhf(u));
}

// ---------------- GEMM: C[m,n] = epi( sum_k A[m,k] * W[n,k] ) --------------
// BM=BN=128, BK=8, 256 threads, 8x8 per-thread microtile (4+4 split).
template <bool GELU, bool RES, bool BIAS>
__global__ __launch_bounds__(256)
void gemm_kernel(const float* __restrict__ A, const float* __restrict__ W,
                 const float* __restrict__ bias, const float* __restrict__ resid,
                 float* __restrict__ C, int Mr, int N, int K)
{
    __shared__ float As[8][128];
    __shared__ float Bs[8][128];

    const int bm = blockIdx.y, bn = blockIdx.x;
    const int t  = threadIdx.x;
    const int tx = t & 15;       // n-direction
    const int ty = t >> 4;       // m-direction
    const int lrow = t >> 1;     // 0..127 (load row)
    const int lcol = (t & 1) * 4;

    const int arow = bm * 128 + lrow;
    const bool aval = arow < Mr;
    const float* Aptr = A + (size_t)(aval ? arow : 0) * K + lcol;
    const float* Wptr = W + (size_t)(bn * 128 + lrow) * K + lcol;

    float acc[8][8];
#pragma unroll
    for (int i = 0; i < 8; i++)
#pragma unroll
        for (int j = 0; j < 8; j++) acc[i][j] = 0.f;

    for (int k0 = 0; k0 < K; k0 += 8) {
        float4 av = aval ? *(const float4*)(Aptr + k0) : make_float4(0.f, 0.f, 0.f, 0.f);
        float4 wv = *(const float4*)(Wptr + k0);
        __syncthreads();
        As[lcol + 0][lrow] = av.x;
        As[lcol + 1][lrow] = av.y;
        As[lcol + 2][lrow] = av.z;
        As[lcol + 3][lrow] = av.w;
        Bs[lcol + 0][lrow] = wv.x;
        Bs[lcol + 1][lrow] = wv.y;
        Bs[lcol + 2][lrow] = wv.z;
        Bs[lcol + 3][lrow] = wv.w;
        __syncthreads();
#pragma unroll
        for (int kk = 0; kk < 8; kk++) {
            float4 a0 = *(const float4*)&As[kk][ty * 4];
            float4 a1 = *(const float4*)&As[kk][ty * 4 + 64];
            float4 b0 = *(const float4*)&Bs[kk][tx * 4];
            float4 b1 = *(const float4*)&Bs[kk][tx * 4 + 64];
            float ar[8] = {a0.x, a0.y, a0.z, a0.w, a1.x, a1.y, a1.z, a1.w};
            float br[8] = {b0.x, b0.y, b0.z, b0.w, b1.x, b1.y, b1.z, b1.w};
#pragma unroll
            for (int i = 0; i < 8; i++)
#pragma unroll
                for (int j = 0; j < 8; j++)
                    acc[i][j] = fmaf(ar[i], br[j], acc[i][j]);
        }
    }

#pragma unroll
    for (int ih = 0; ih < 2; ih++)
#pragma unroll
        for (int i = 0; i < 4; i++) {
            int row = bm * 128 + ih * 64 + ty * 4 + i;
            if (row >= Mr) continue;
#pragma unroll
            for (int jh = 0; jh < 2; jh++)
#pragma unroll
                for (int j = 0; j < 4; j++) {
                    int col = bn * 128 + jh * 64 + tx * 4 + j;
                    float v = acc[ih * 4 + i][jh * 4 + j];
                    if (BIAS) v += bias[col];
                    if (GELU) v = gelu_tanh(v);
                    if (RES)  v += resid[(size_t)row * N + col];
                    C[(size_t)row * N + col] = v;
                }
        }
}

// ---------------- flash attention (causal), one head x 64-query block ------
// blockDim 256: thread (ty,tx) = 4 query rows x 4 key-cols (scores)
//                              = 4 query rows x 4 dims     (output)
#define KPAD 68
__global__ __launch_bounds__(256)
void attn_kernel(const float* __restrict__ Q, const float* __restrict__ K,
                 const float* __restrict__ V, float* __restrict__ O)
{
    extern __shared__ float sm[];
    float* Qs = sm;                  // 64*64
    float* Ks = Qs + 64 * 64;        // 64*KPAD
    float* Vs = Ks + 64 * KPAD;      // 64*KPAD
    float* Ps = Vs + 64 * KPAD;      // 64*KPAD

    const int qb = blockIdx.x, h = blockIdx.y;
    const int t  = threadIdx.x;
    const int tx = t & 15, ty = t >> 4;
    const int lrow = t >> 2;
    const int lcg  = (t & 3) * 16;

    // load Q block (64x64)
    {
        const float4* s4 = (const float4*)(Q + (size_t)(qb * 64 + lrow) * DIM + h * HD + lcg);
        float4* dq = (float4*)(Qs + lrow * 64 + lcg);
        dq[0] = s4[0]; dq[1] = s4[1]; dq[2] = s4[2]; dq[3] = s4[3];
    }

    float m[4], l[4], o[4][4];
#pragma unroll
    for (int i = 0; i < 4; i++) {
        m[i] = -1e30f; l[i] = 0.f;
#pragma unroll
        for (int j = 0; j < 4; j++) o[i][j] = 0.f;
    }
    const float scale = 0.125f; // 1/sqrt(64)

    for (int kb = 0; kb <= qb; kb++) {
        __syncthreads();
        // load K, V blocks
        {
            const float4* ks = (const float4*)(K + (size_t)(kb * 64 + lrow) * DIM + h * HD + lcg);
            const float4* vs = (const float4*)(V + (size_t)(kb * 64 + lrow) * DIM + h * HD + lcg);
            float4* kd = (float4*)(Ks + lrow * KPAD + lcg);
            float4* vd = (float4*)(Vs + lrow * KPAD + lcg);
#pragma unroll
            for (int i = 0; i < 4; i++) { kd[i] = ks[i]; vd[i] = vs[i]; }
        }
        __syncthreads();

        // scores: sv[i][j] = Q[ty*4+i] . K[tx*4+j]
        float sv[4][4];
#pragma unroll
        for (int i = 0; i < 4; i++)
#pragma unroll
            for (int j = 0; j < 4; j++) sv[i][j] = 0.f;
#pragma unroll 4
        for (int k = 0; k < 64; k += 4) {
            float4 qa[4], kb4[4];
#pragma unroll
            for (int i = 0; i < 4; i++) qa[i]  = *(const float4*)(Qs + (ty * 4 + i) * 64 + k);
#pragma unroll
            for (int j = 0; j < 4; j++) kb4[j] = *(const float4*)(Ks + (tx * 4 + j) * KPAD + k);
#pragma unroll
            for (int i = 0; i < 4; i++)
#pragma unroll
                for (int j = 0; j < 4; j++)
                    sv[i][j] += qa[i].x * kb4[j].x + qa[i].y * kb4[j].y +
                                qa[i].z * kb4[j].z + qa[i].w * kb4[j].w;
        }

        // scale + causal mask (only diagonal block needs it)
#pragma unroll
        for (int i = 0; i < 4; i++)
#pragma unroll
            for (int j = 0; j < 4; j++) {
                float s = sv[i][j] * scale;
                if (kb == qb && (tx * 4 + j) > (ty * 4 + i)) s = -1e30f;
                sv[i][j] = s;
            }

        // online softmax per row (reduce across the 16 tx lanes)
#pragma unroll
        for (int i = 0; i < 4; i++) {
            float lm = fmaxf(fmaxf(sv[i][0], sv[i][1]), fmaxf(sv[i][2], sv[i][3]));
#pragma unroll
            for (int off = 1; off < 16; off <<= 1)
                lm = fmaxf(lm, __shfl_xor_sync(0xffffffffu, lm, off));
            float mn   = fmaxf(m[i], lm);
            float corr = __expf(m[i] - mn);
            float ls = 0.f;
#pragma unroll
            for (int j = 0; j < 4; j++) {
                float p = __expf(sv[i][j] - mn);
                sv[i][j] = p;
                ls += p;
            }
#pragma unroll
            for (int off = 1; off < 16; off <<= 1)
                ls += __shfl_xor_sync(0xffffffffu, ls, off);
            l[i] = l[i] * corr + ls;
            m[i] = mn;
#pragma unroll
            for (int j = 0; j < 4; j++) o[i][j] *= corr;
            *(float4*)(Ps + (ty * 4 + i) * KPAD + tx * 4) =
                make_float4(sv[i][0], sv[i][1], sv[i][2], sv[i][3]);
        }
        __syncthreads();

        // O += P @ V   (thread dims: tx*4..+4)
#pragma unroll 4
        for (int j = 0; j < 64; j++) {
            float4 v4 = *(const float4*)(Vs + j * KPAD + tx * 4);
#pragma unroll
            for (int i = 0; i < 4; i++) {
                float p = Ps[(ty * 4 + i) * KPAD + j];
                o[i][0] = fmaf(p, v4.x, o[i][0]);
                o[i][1] = fmaf(p, v4.y, o[i][1]);
                o[i][2] = fmaf(p, v4.z, o[i][2]);
                o[i][3] = fmaf(p, v4.w, o[i][3]);
            }
        }
    }

#pragma unroll
    for (int i = 0; i < 4; i++) {
        float inv = 1.0f / l[i];
        int row = qb * 64 + ty * 4 + i;
#pragma unroll
        for (int j = 0; j < 4; j++)
            O[(size_t)row * DIM + h * HD + tx * 4 + j] = o[i][j] * inv;
    }
}

// ---------------- launch ----------------------------------------------------
extern "C" void kernel_launch(void* const* d_in, const int* in_sizes, int n_in,
                              void* d_out, int out_size)
{
    const int*   tokens = (const int*)  d_in[0];
    const float* emb    = (const float*)d_in[1];
    const float* pos    = (const float*)d_in[2];
    const float* mem    = (const float*)d_in[3];
    const float* ln1_s  = (const float*)d_in[4];
    const float* ln1_b  = (const float*)d_in[5];
    const float* wq     = (const float*)d_in[6];
    const float* wk     = (const float*)d_in[7];
    const float* wv     = (const float*)d_in[8];
    const float* wo     = (const float*)d_in[9];
    const float* ln2_s  = (const float*)d_in[10];
    const float* ln2_b  = (const float*)d_in[11];
    const float* w1     = (const float*)d_in[12];
    const float* b1     = (const float*)d_in[13];
    const float* w2     = (const float*)d_in[14];
    const float* b2     = (const float*)d_in[15];
    const float* lnm_s  = (const float*)d_in[16];
    const float* lnm_b  = (const float*)d_in[17];

    float *X, *Nb, *Q, *Kb, *Vb, *Ao, *F;
    cudaGetSymbolAddress((void**)&X,  g_X);
    cudaGetSymbolAddress((void**)&Nb, g_N);
    cudaGetSymbolAddress((void**)&Q,  g_Q);
    cudaGetSymbolAddress((void**)&Kb, g_K);
    cudaGetSymbolAddress((void**)&Vb, g_V);
    cudaGetSymbolAddress((void**)&Ao, g_A);
    cudaGetSymbolAddress((void**)&F,  g_F);

    const int ATTN_SMEM = (64 * 64 + 3 * 64 * KPAD) * (int)sizeof(float); // 68608 B
    cudaFuncSetAttribute(attn_kernel, cudaFuncAttributeMaxDynamicSharedMemorySize, ATTN_SMEM);

    embed_kernel<<<(S_TOT * DIM + 255) / 256, 256>>>(tokens, emb, pos, mem, X);

    const dim3 gProj(DIM / 128, (S_TOT + 127) / 128);   // (6, 17)
    const dim3 gFF1 (HID / 128, (S_TOT + 127) / 128);   // (24, 17)

    for (int l = 0; l < NLAYER; l++) {
        ln_kernel<<<S_TOT, 256>>>(X, ln1_s + l * DIM, ln1_b + l * DIM, Nb, 0);

        gemm_kernel<false, false, false><<<gProj, 256>>>(
            Nb, wq + (size_t)l * DIM * DIM, nullptr, nullptr, Q, S_TOT, DIM, DIM);
        gemm_kernel<false, false, false><<<gProj, 256>>>(
            Nb, wk + (size_t)l * DIM * DIM, nullptr, nullptr, Kb, S_TOT, DIM, DIM);
        gemm_kernel<false, false, false><<<gProj, 256>>>(
            Nb, wv + (size_t)l * DIM * DIM, nullptr, nullptr, Vb, S_TOT, DIM, DIM);

        attn_kernel<<<dim3(S_TOT / 64, NHEAD), 256, ATTN_SMEM>>>(Q, Kb, Vb, Ao);

        gemm_kernel<false, true, false><<<gProj, 256>>>(
            Ao, wo + (size_t)l * DIM * DIM, nullptr, X, X, S_TOT, DIM, DIM);

        ln_kernel<<<S_TOT, 256>>>(X, ln2_s + l * DIM, ln2_b + l * DIM, Nb, 0);

        gemm_kernel<true, false, true><<<gFF1, 256>>>(
            Nb, w1 + (size_t)l * HID * DIM, b1 + l * HID, nullptr, F, S_TOT, HID, DIM);
        gemm_kernel<false, true, true><<<gProj, 256>>>(
            F, w2 + (size_t)l * DIM * HID, b2 + l * DIM, X, X, S_TOT, DIM, HID);
    }

    // final layernorm, last MEMN rows only, straight into d_out
    ln_kernel<<<MEMN, 256>>>(X, lnm_s, lnm_b, (float*)d_out, S_TOT - MEMN);
}

// round 3
// speedup vs baseline: 1.6410x; 1.6410x over previous
#include <cuda_runtime.h>
#include <cuda_bf16.h>
#include <cstdint>

#define S_TOT 2112          // 64 mem + 2048 tokens
#define MEMN  64
#define DIM   768
#define HID   3072
#define NHEAD 12
#define HD    64
#define NLAYER 4

// ---------------- scratch (device globals; no allocation allowed) ----------
__device__ __align__(16) float g_X [S_TOT * DIM];
__device__ __align__(16) float g_N [S_TOT * DIM];
__device__ __align__(16) float g_Q [S_TOT * DIM];
__device__ __align__(16) float g_K [S_TOT * DIM];
__device__ __align__(16) float g_V [S_TOT * DIM];
__device__ __align__(16) float g_A [S_TOT * DIM];
__device__ __align__(16) float g_F [S_TOT * HID];

// ---------------- embedding ------------------------------------------------
__global__ void embed_kernel(const int* __restrict__ tokens,
                             const float* __restrict__ emb,
                             const float* __restrict__ pos,
                             const float* __restrict__ mem,
                             float* __restrict__ X)
{
    int idx = blockIdx.x * 256 + threadIdx.x;
    if (idx >= S_TOT * DIM) return;
    int s = idx / DIM;
    int d = idx - s * DIM;
    if (s < MEMN) {
        X[idx] = mem[s * DIM + d];
    } else {
        int t = s - MEMN;
        X[idx] = emb[tokens[t] * DIM + d] + pos[t * DIM + d];
    }
}

// ---------------- layernorm (one row per block, 256 threads) ---------------
__global__ void ln_kernel(const float* __restrict__ X,
                          const float* __restrict__ g,
                          const float* __restrict__ bt,
                          float* __restrict__ out,
                          int in_off)
{
    int row = blockIdx.x + in_off;
    const float* x = X + (size_t)row * DIM;
    int t = threadIdx.x;
    float v0 = x[t], v1 = x[t + 256], v2 = x[t + 512];
    float s = v0 + v1 + v2;
    float q = v0 * v0 + v1 * v1 + v2 * v2;
#pragma unroll
    for (int off = 16; off; off >>= 1) {
        s += __shfl_xor_sync(0xffffffffu, s, off);
        q += __shfl_xor_sync(0xffffffffu, q, off);
    }
    __shared__ float rs[8], rq[8];
    __shared__ float mean_sh, inv_sh;
    int w = t >> 5;
    if ((t & 31) == 0) { rs[w] = s; rq[w] = q; }
    __syncthreads();
    if (t == 0) {
        float S = 0.f, Q = 0.f;
#pragma unroll
        for (int i = 0; i < 8; i++) { S += rs[i]; Q += rq[i]; }
        float mean = S * (1.0f / DIM);
        float var  = Q * (1.0f / DIM) - mean * mean;
        mean_sh = mean;
        inv_sh  = rsqrtf(var + 1e-5f);
    }
    __syncthreads();
    float mean = mean_sh, inv = inv_sh;
    float* o = out + (size_t)blockIdx.x * DIM;
    o[t]       = (v0 - mean) * inv * g[t]       + bt[t];
    o[t + 256] = (v1 - mean) * inv * g[t + 256] + bt[t + 256];
    o[t + 512] = (v2 - mean) * inv * g[t + 512] + bt[t + 512];
}

// ---------------- gelu (tanh approximation) --------------------------------
__device__ __forceinline__ float gelu_tanh(float x)
{
    const float c = 0.7978845608028654f;
    float u = c * (x + 0.044715f * x * x * x);
    return 0.5f * x * (1.0f + tanhf(u));
}

// =================== mma.sync helpers =======================================
__device__ __forceinline__ uint32_t smem_u32(const void* p) {
    uint32_t a;
    asm("{ .reg .u64 t; cvta.to.shared.u64 t, %1; cvt.u32.u64 %0, t; }"
        : "=r"(a) : "l"(p));
    return a;
}
__device__ __forceinline__ void ldsm_x4(uint32_t* r, uint32_t addr) {
    asm volatile("ldmatrix.sync.aligned.m8n8.x4.shared.b16 {%0,%1,%2,%3}, [%4];"
                 : "=r"(r[0]), "=r"(r[1]), "=r"(r[2]), "=r"(r[3]) : "r"(addr));
}
__device__ __forceinline__ void mma16816(float* c, const uint32_t* a,
                                         const uint32_t b0, const uint32_t b1) {
    asm volatile("mma.sync.aligned.m16n8k16.row.col.f32.bf16.bf16.f32 "
                 "{%0,%1,%2,%3}, {%4,%5,%6,%7}, {%8,%9}, {%0,%1,%2,%3};"
                 : "+f"(c[0]), "+f"(c[1]), "+f"(c[2]), "+f"(c[3])
                 : "r"(a[0]), "r"(a[1]), "r"(a[2]), "r"(a[3]), "r"(b0), "r"(b1));
}
// split fp32x4 -> packed bf16 hi (uint2) and lo (uint2)
__device__ __forceinline__ void split4(float4 v, uint2& hi, uint2& lo)
{
    __nv_bfloat16 h0 = __float2bfloat16(v.x);
    __nv_bfloat16 h1 = __float2bfloat16(v.y);
    __nv_bfloat16 h2 = __float2bfloat16(v.z);
    __nv_bfloat16 h3 = __float2bfloat16(v.w);
    __nv_bfloat16 l0 = __float2bfloat16(v.x - __bfloat162float(h0));
    __nv_bfloat16 l1 = __float2bfloat16(v.y - __bfloat162float(h1));
    __nv_bfloat16 l2 = __float2bfloat16(v.z - __bfloat162float(h2));
    __nv_bfloat16 l3 = __float2bfloat16(v.w - __bfloat162float(h3));
    hi.x = (uint32_t)__bfloat16_as_ushort(h1) << 16 | __bfloat16_as_ushort(h0);
    hi.y = (uint32_t)__bfloat16_as_ushort(h3) << 16 | __bfloat16_as_ushort(h2);
    lo.x = (uint32_t)__bfloat16_as_ushort(l1) << 16 | __bfloat16_as_ushort(l0);
    lo.y = (uint32_t)__bfloat16_as_ushort(l3) << 16 | __bfloat16_as_ushort(l2);
}

// =================== bf16x3 tensor-core GEMM ================================
// C[m,n] = epi( sum_k A[m,k] * W[n,k] ), A:[Mr,K] fp32, W:[N,K] fp32.
// BM=BN=128, BK=32, 8 warps (2x4), each warp 64x32 via m16n8k16 tiles.
// Smem: per stage {Ah, Al, Bh, Bl}, each 128 x 40(pitch) bf16 = 10240 B.
#define GPITCH 40
#define GMAT   10240
#define GSTAGE (4 * GMAT)           // 40960
#define GEMM_SMEM (2 * GSTAGE)      // 81920

template <bool GELU, bool RES, bool BIAS>
__global__ __launch_bounds__(256, 1)
void gemm_tc(const float* __restrict__ A, const float* __restrict__ W,
             const float* __restrict__ bias, const float* __restrict__ resid,
             float* __restrict__ C, int Mr, int N, int K)
{
    extern __shared__ char smem[];
    const uint32_t sb = smem_u32(smem);
    const int tid = threadIdx.x, wid = tid >> 5, lane = tid & 31;
    const int bm = blockIdx.y, bn = blockIdx.x;
    const int wm = (wid >> 2) * 64;     // warp m offset
    const int wn = (wid & 3) * 32;      // warp n offset

    // loader mapping: row = tid>>1, col base = (tid&1)*16, 4x float4
    const int lr = tid >> 1;
    const int lc = (tid & 1) * 16;
    const bool aval = (bm * 128 + lr) < Mr;
    const float* Ap = A + (size_t)(bm * 128 + lr) * K + lc;
    const float* Wp = W + (size_t)(bn * 128 + lr) * K + lc;

    float acc[4][4][4];
#pragma unroll
    for (int i = 0; i < 4; i++)
#pragma unroll
        for (int j = 0; j < 4; j++)
#pragma unroll
            for (int k = 0; k < 4; k++) acc[i][j][k] = 0.f;

    const int KT = K >> 5;
    float4 pa[4], pb[4];

    // prefetch tile 0
#pragma unroll
    for (int i = 0; i < 4; i++) {
        pa[i] = aval ? *(const float4*)(Ap + i * 4) : make_float4(0.f, 0.f, 0.f, 0.f);
        pb[i] = *(const float4*)(Wp + i * 4);
    }

    for (int kt = 0; kt < KT; kt++) {
        const int s = kt & 1;
        char* stg = smem + s * GSTAGE;
        // ---- store converted tile to smem ----
#pragma unroll
        for (int i = 0; i < 4; i++) {
            uint2 hi, lo;
            split4(pa[i], hi, lo);
            int off = (lr * GPITCH + lc + i * 4) * 2;
            *(uint2*)(stg + off)            = hi;   // Ah
            *(uint2*)(stg + GMAT + off)     = lo;   // Al
            split4(pb[i], hi, lo);
            *(uint2*)(stg + 2 * GMAT + off) = hi;   // Bh
            *(uint2*)(stg + 3 * GMAT + off) = lo;   // Bl
        }
        __syncthreads();

        // ---- prefetch next tile ----
        if (kt + 1 < KT) {
            const int kb = (kt + 1) * 32;
#pragma unroll
            for (int i = 0; i < 4; i++) {
                pa[i] = aval ? *(const float4*)(Ap + kb + i * 4)
                             : make_float4(0.f, 0.f, 0.f, 0.f);
                pb[i] = *(const float4*)(Wp + kb + i * 4);
            }
        }

        // ---- compute on stage s ----
        const uint32_t base = sb + s * GSTAGE;
#pragma unroll
        for (int ks = 0; ks < 2; ks++) {
            const int k0 = ks * 16;
            uint32_t aH[4][4], aL[4][4], bH[2][4], bL[2][4];
            // A fragments: lanes 0-15 -> rows 0-15 @k0; 16-31 -> rows @k0+8
            const int arow = wm + (lane & 15);
            const int acol = k0 + ((lane >> 4) << 3);
#pragma unroll
            for (int mt = 0; mt < 4; mt++) {
                uint32_t ad = base + ((arow + mt * 16) * GPITCH + acol) * 2;
                ldsm_x4(aH[mt], ad);
                ldsm_x4(aL[mt], ad + GMAT);
            }
            // B fragments: lanes 0-7: n0-7@k0; 8-15: n0-7@k0+8; 16-23: n8-15@k0; 24-31: n8-15@k0+8
            const int brow = wn + (lane & 7) + ((lane >> 4) << 3);
            const int bcol = k0 + (((lane >> 3) & 1) << 3);
#pragma unroll
            for (int n2 = 0; n2 < 2; n2++) {
                uint32_t bd = base + 2 * GMAT + ((brow + n2 * 16) * GPITCH + bcol) * 2;
                ldsm_x4(bH[n2], bd);
                ldsm_x4(bL[n2], bd + GMAT);
            }
#pragma unroll
            for (int mt = 0; mt < 4; mt++)
#pragma unroll
                for (int nt = 0; nt < 4; nt++) {
                    const int n2 = nt >> 1, hb = (nt & 1) * 2;
                    mma16816(acc[mt][nt], aH[mt], bH[n2][hb], bH[n2][hb + 1]);
                    mma16816(acc[mt][nt], aH[mt], bL[n2][hb], bL[n2][hb + 1]);
                    mma16816(acc[mt][nt], aL[mt], bH[n2][hb], bH[n2][hb + 1]);
                }
        }
        __syncthreads();
    }

    // ---- epilogue: direct stores ----
#pragma unroll
    for (int mt = 0; mt < 4; mt++) {
        const int r0 = bm * 128 + wm + mt * 16 + (lane >> 2);
#pragma unroll
        for (int nt = 0; nt < 4; nt++) {
            const int col = bn * 128 + wn + nt * 8 + (lane & 3) * 2;
            float* c = acc[mt][nt];
            float bx = 0.f, by = 0.f;
            if (BIAS) { float2 bv = *(const float2*)(bias + col); bx = bv.x; by = bv.y; }
            if (r0 < Mr) {
                float v0 = c[0], v1 = c[1];
                if (BIAS) { v0 += bx; v1 += by; }
                if (GELU) { v0 = gelu_tanh(v0); v1 = gelu_tanh(v1); }
                if (RES)  { float2 rv = *(const float2*)(resid + (size_t)r0 * N + col);
                            v0 += rv.x; v1 += rv.y; }
                *(float2*)(C + (size_t)r0 * N + col) = make_float2(v0, v1);
            }
            const int r1 = r0 + 8;
            if (r1 < Mr) {
                float v0 = c[2], v1 = c[3];
                if (BIAS) { v0 += bx; v1 += by; }
                if (GELU) { v0 = gelu_tanh(v0); v1 = gelu_tanh(v1); }
                if (RES)  { float2 rv = *(const float2*)(resid + (size_t)r1 * N + col);
                            v0 += rv.x; v1 += rv.y; }
                *(float2*)(C + (size_t)r1 * N + col) = make_float2(v0, v1);
            }
        }
    }
}

// ---------------- flash attention (causal), one head x 64-query block ------
#define KPAD 68
__global__ __launch_bounds__(256)
void attn_kernel(const float* __restrict__ Q, const float* __restrict__ K,
                 const float* __restrict__ V, float* __restrict__ O)
{
    extern __shared__ float sm[];
    float* Qs = sm;
    float* Ks = Qs + 64 * 64;
    float* Vs = Ks + 64 * KPAD;
    float* Ps = Vs + 64 * KPAD;

    const int qb = blockIdx.x, h = blockIdx.y;
    const int t  = threadIdx.x;
    const int tx = t & 15, ty = t >> 4;
    const int lrow = t >> 2;
    const int lcg  = (t & 3) * 16;

    {
        const float4* s4 = (const float4*)(Q + (size_t)(qb * 64 + lrow) * DIM + h * HD + lcg);
        float4* dq = (float4*)(Qs + lrow * 64 + lcg);
        dq[0] = s4[0]; dq[1] = s4[1]; dq[2] = s4[2]; dq[3] = s4[3];
    }

    float m[4], l[4], o[4][4];
#pragma unroll
    for (int i = 0; i < 4; i++) {
        m[i] = -1e30f; l[i] = 0.f;
#pragma unroll
        for (int j = 0; j < 4; j++) o[i][j] = 0.f;
    }
    const float scale = 0.125f;

    for (int kb = 0; kb <= qb; kb++) {
        __syncthreads();
        {
            const float4* ks = (const float4*)(K + (size_t)(kb * 64 + lrow) * DIM + h * HD + lcg);
            const float4* vs = (const float4*)(V + (size_t)(kb * 64 + lrow) * DIM + h * HD + lcg);
            float4* kd = (float4*)(Ks + lrow * KPAD + lcg);
            float4* vd = (float4*)(Vs + lrow * KPAD + lcg);
#pragma unroll
            for (int i = 0; i < 4; i++) { kd[i] = ks[i]; vd[i] = vs[i]; }
        }
        __syncthreads();

        float sv[4][4];
#pragma unroll
        for (int i = 0; i < 4; i++)
#pragma unroll
            for (int j = 0; j < 4; j++) sv[i][j] = 0.f;
#pragma unroll 4
        for (int k = 0; k < 64; k += 4) {
            float4 qa[4], kb4[4];
#pragma unroll
            for (int i = 0; i < 4; i++) qa[i]  = *(const float4*)(Qs + (ty * 4 + i) * 64 + k);
#pragma unroll
            for (int j = 0; j < 4; j++) kb4[j] = *(const float4*)(Ks + (tx * 4 + j) * KPAD + k);
#pragma unroll
            for (int i = 0; i < 4; i++)
#pragma unroll
                for (int j = 0; j < 4; j++)
                    sv[i][j] += qa[i].x * kb4[j].x + qa[i].y * kb4[j].y +
                                qa[i].z * kb4[j].z + qa[i].w * kb4[j].w;
        }

#pragma unroll
        for (int i = 0; i < 4; i++)
#pragma unroll
            for (int j = 0; j < 4; j++) {
                float s = sv[i][j] * scale;
                if (kb == qb && (tx * 4 + j) > (ty * 4 + i)) s = -1e30f;
                sv[i][j] = s;
            }

#pragma unroll
        for (int i = 0; i < 4; i++) {
            float lm = fmaxf(fmaxf(sv[i][0], sv[i][1]), fmaxf(sv[i][2], sv[i][3]));
#pragma unroll
            for (int off = 1; off < 16; off <<= 1)
                lm = fmaxf(lm, __shfl_xor_sync(0xffffffffu, lm, off));
            float mn   = fmaxf(m[i], lm);
            float corr = __expf(m[i] - mn);
            float ls = 0.f;
#pragma unroll
            for (int j = 0; j < 4; j++) {
                float p = __expf(sv[i][j] - mn);
                sv[i][j] = p;
                ls += p;
            }
#pragma unroll
            for (int off = 1; off < 16; off <<= 1)
                ls += __shfl_xor_sync(0xffffffffu, ls, off);
            l[i] = l[i] * corr + ls;
            m[i] = mn;
#pragma unroll
            for (int j = 0; j < 4; j++) o[i][j] *= corr;
            *(float4*)(Ps + (ty * 4 + i) * KPAD + tx * 4) =
                make_float4(sv[i][0], sv[i][1], sv[i][2], sv[i][3]);
        }
        __syncthreads();

#pragma unroll 4
        for (int j = 0; j < 64; j++) {
            float4 v4 = *(const float4*)(Vs + j * KPAD + tx * 4);
#pragma unroll
            for (int i = 0; i < 4; i++) {
                float p = Ps[(ty * 4 + i) * KPAD + j];
                o[i][0] = fmaf(p, v4.x, o[i][0]);
                o[i][1] = fmaf(p, v4.y, o[i][1]);
                o[i][2] = fmaf(p, v4.z, o[i][2]);
                o[i][3] = fmaf(p, v4.w, o[i][3]);
            }
        }
    }

#pragma unroll
    for (int i = 0; i < 4; i++) {
        float inv = 1.0f / l[i];
        int row = qb * 64 + ty * 4 + i;
#pragma unroll
        for (int j = 0; j < 4; j++)
            O[(size_t)row * DIM + h * HD + tx * 4 + j] = o[i][j] * inv;
    }
}

// ---------------- launch ----------------------------------------------------
extern "C" void kernel_launch(void* const* d_in, const int* in_sizes, int n_in,
                              void* d_out, int out_size)
{
    const int*   tokens = (const int*)  d_in[0];
    const float* emb    = (const float*)d_in[1];
    const float* pos    = (const float*)d_in[2];
    const float* mem    = (const float*)d_in[3];
    const float* ln1_s  = (const float*)d_in[4];
    const float* ln1_b  = (const float*)d_in[5];
    const float* wq     = (const float*)d_in[6];
    const float* wk     = (const float*)d_in[7];
    const float* wv     = (const float*)d_in[8];
    const float* wo     = (const float*)d_in[9];
    const float* ln2_s  = (const float*)d_in[10];
    const float* ln2_b  = (const float*)d_in[11];
    const float* w1     = (const float*)d_in[12];
    const float* b1     = (const float*)d_in[13];
    const float* w2     = (const float*)d_in[14];
    const float* b2     = (const float*)d_in[15];
    const float* lnm_s  = (const float*)d_in[16];
    const float* lnm_b  = (const float*)d_in[17];

    float *X, *Nb, *Q, *Kb, *Vb, *Ao, *F;
    cudaGetSymbolAddress((void**)&X,  g_X);
    cudaGetSymbolAddress((void**)&Nb, g_N);
    cudaGetSymbolAddress((void**)&Q,  g_Q);
    cudaGetSymbolAddress((void**)&Kb, g_K);
    cudaGetSymbolAddress((void**)&Vb, g_V);
    cudaGetSymbolAddress((void**)&Ao, g_A);
    cudaGetSymbolAddress((void**)&F,  g_F);

    const int ATTN_SMEM = (64 * 64 + 3 * 64 * KPAD) * (int)sizeof(float);
    cudaFuncSetAttribute(attn_kernel, cudaFuncAttributeMaxDynamicSharedMemorySize, ATTN_SMEM);
    cudaFuncSetAttribute(gemm_tc<false, false, false>, cudaFuncAttributeMaxDynamicSharedMemorySize, GEMM_SMEM);
    cudaFuncSetAttribute(gemm_tc<false, true,  false>, cudaFuncAttributeMaxDynamicSharedMemorySize, GEMM_SMEM);
    cudaFuncSetAttribute(gemm_tc<true,  false, true >, cudaFuncAttributeMaxDynamicSharedMemorySize, GEMM_SMEM);
    cudaFuncSetAttribute(gemm_tc<false, true,  true >, cudaFuncAttributeMaxDynamicSharedMemorySize, GEMM_SMEM);

    embed_kernel<<<(S_TOT * DIM + 255) / 256, 256>>>(tokens, emb, pos, mem, X);

    const dim3 gProj(DIM / 128, (S_TOT + 127) / 128);   // (6, 17)
    const dim3 gFF1 (HID / 128, (S_TOT + 127) / 128);   // (24, 17)

    for (int l = 0; l < NLAYER; l++) {
        ln_kernel<<<S_TOT, 256>>>(X, ln1_s + l * DIM, ln1_b + l * DIM, Nb, 0);

        gemm_tc<false, false, false><<<gProj, 256, GEMM_SMEM>>>(
            Nb, wq + (size_t)l * DIM * DIM, nullptr, nullptr, Q, S_TOT, DIM, DIM);
        gemm_tc<false, false, false><<<gProj, 256, GEMM_SMEM>>>(
            Nb, wk + (size_t)l * DIM * DIM, nullptr, nullptr, Kb, S_TOT, DIM, DIM);
        gemm_tc<false, false, false><<<gProj, 256, GEMM_SMEM>>>(
            Nb, wv + (size_t)l * DIM * DIM, nullptr, nullptr, Vb, S_TOT, DIM, DIM);

        attn_kernel<<<dim3(S_TOT / 64, NHEAD), 256, ATTN_SMEM>>>(Q, Kb, Vb, Ao);

        gemm_tc<false, true, false><<<gProj, 256, GEMM_SMEM>>>(
            Ao, wo + (size_t)l * DIM * DIM, nullptr, X, X, S_TOT, DIM, DIM);

        ln_kernel<<<S_TOT, 256>>>(X, ln2_s + l * DIM, ln2_b + l * DIM, Nb, 0);

        gemm_tc<true, false, true><<<gFF1, 256, GEMM_SMEM>>>(
            Nb, w1 + (size_t)l * HID * DIM, b1 + l * HID, nullptr, F, S_TOT, HID, DIM);
        gemm_tc<false, true, true><<<gProj, 256, GEMM_SMEM>>>(
            F, w2 + (size_t)l * DIM * HID, b2 + l * DIM, X, X, S_TOT, DIM, HID);
    }

    ln_kernel<<<MEMN, 256>>>(X, lnm_s, lnm_b, (float*)d_out, S_TOT - MEMN);
}

// round 4
// speedup vs baseline: 1.8390x; 1.1207x over previous
#include <cuda_runtime.h>
#include <cuda_bf16.h>
#include <cstdint>

#define S_TOT 2112          // 64 mem + 2048 tokens
#define MEMN  64
#define DIM   768
#define HID   3072
#define NHEAD 12
#define HD    64
#define NLAYER 4

// ---------------- scratch (device globals; no allocation allowed) ----------
__device__ __align__(16) float g_X [S_TOT * DIM];
__device__ __align__(16) float g_Q [S_TOT * DIM];
__device__ __align__(16) float g_K [S_TOT * DIM];
__device__ __align__(16) float g_V [S_TOT * DIM];

__device__ __align__(16) __nv_bfloat16 g_Nh[S_TOT * DIM];
__device__ __align__(16) __nv_bfloat16 g_Nl[S_TOT * DIM];
__device__ __align__(16) __nv_bfloat16 g_Ahp[S_TOT * DIM];
__device__ __align__(16) __nv_bfloat16 g_Alp[S_TOT * DIM];
__device__ __align__(16) __nv_bfloat16 g_Fh[S_TOT * HID];
__device__ __align__(16) __nv_bfloat16 g_Fl[S_TOT * HID];

// preconverted weights (hi/lo bf16), all layers
#define WSZ_P  (NLAYER * DIM * DIM)     // 2359296 (per proj tensor, all layers)
#define WSZ_FF (NLAYER * HID * DIM)     // 9437184
#define OFF_WQ 0
#define OFF_WK (OFF_WQ + WSZ_P)
#define OFF_WV (OFF_WK + WSZ_P)
#define OFF_WO (OFF_WV + WSZ_P)
#define OFF_W1 (OFF_WO + WSZ_P)
#define OFF_W2 (OFF_W1 + WSZ_FF)
#define WTOT   (OFF_W2 + WSZ_FF)        // 28311552
__device__ __align__(16) __nv_bfloat16 g_Wh[WTOT];
__device__ __align__(16) __nv_bfloat16 g_Wl[WTOT];

// =================== helpers ================================================
__device__ __forceinline__ uint32_t smem_u32(const void* p) {
    uint32_t a;
    asm("{ .reg .u64 t; cvta.to.shared.u64 t, %1; cvt.u32.u64 %0, t; }"
        : "=r"(a) : "l"(p));
    return a;
}
__device__ __forceinline__ void ldsm_x4(uint32_t* r, uint32_t addr) {
    asm volatile("ldmatrix.sync.aligned.m8n8.x4.shared.b16 {%0,%1,%2,%3}, [%4];"
                 : "=r"(r[0]), "=r"(r[1]), "=r"(r[2]), "=r"(r[3]) : "r"(addr));
}
__device__ __forceinline__ void mma16816(float* c, const uint32_t* a,
                                         const uint32_t b0, const uint32_t b1) {
    asm volatile("mma.sync.aligned.m16n8k16.row.col.f32.bf16.bf16.f32 "
                 "{%0,%1,%2,%3}, {%4,%5,%6,%7}, {%8,%9}, {%0,%1,%2,%3};"
                 : "+f"(c[0]), "+f"(c[1]), "+f"(c[2]), "+f"(c[3])
                 : "r"(a[0]), "r"(a[1]), "r"(a[2]), "r"(a[3]), "r"(b0), "r"(b1));
}
__device__ __forceinline__ void cp_async16(uint32_t dst, const void* src, bool pred) {
    int sz = pred ? 16 : 0;
    asm volatile("cp.async.cg.shared.global [%0], [%1], 16, %2;"
                 :: "r"(dst), "l"(src), "r"(sz) : "memory");
}
#define CP_COMMIT() asm volatile("cp.async.commit_group;" ::: "memory")
#define CP_WAIT2()  asm volatile("cp.async.wait_group 2;" ::: "memory")

// split fp32x4 -> packed bf16 hi (uint2) and lo (uint2)
__device__ __forceinline__ void split4(float4 v, uint2& hi, uint2& lo)
{
    __nv_bfloat16 h0 = __float2bfloat16(v.x);
    __nv_bfloat16 h1 = __float2bfloat16(v.y);
    __nv_bfloat16 h2 = __float2bfloat16(v.z);
    __nv_bfloat16 h3 = __float2bfloat16(v.w);
    __nv_bfloat16 l0 = __float2bfloat16(v.x - __bfloat162float(h0));
    __nv_bfloat16 l1 = __float2bfloat16(v.y - __bfloat162float(h1));
    __nv_bfloat16 l2 = __float2bfloat16(v.z - __bfloat162float(h2));
    __nv_bfloat16 l3 = __float2bfloat16(v.w - __bfloat162float(h3));
    hi.x = (uint32_t)__bfloat16_as_ushort(h1) << 16 | __bfloat16_as_ushort(h0);
    hi.y = (uint32_t)__bfloat16_as_ushort(h3) << 16 | __bfloat16_as_ushort(h2);
    lo.x = (uint32_t)__bfloat16_as_ushort(l1) << 16 | __bfloat16_as_ushort(l0);
    lo.y = (uint32_t)__bfloat16_as_ushort(l3) << 16 | __bfloat16_as_ushort(l2);
}

// ---------------- weight pre-conversion ------------------------------------
__global__ void conv_hl_kernel(const float* __restrict__ s,
                               __nv_bfloat16* __restrict__ dh,
                               __nv_bfloat16* __restrict__ dl, int n4)
{
    int i = blockIdx.x * 256 + threadIdx.x;
    if (i >= n4) return;
    float4 v = ((const float4*)s)[i];
    uint2 hi, lo;
    split4(v, hi, lo);
    ((uint2*)dh)[i] = hi;
    ((uint2*)dl)[i] = lo;
}

// ---------------- embedding ------------------------------------------------
__global__ void embed_kernel(const int* __restrict__ tokens,
                             const float* __restrict__ emb,
                             const float* __restrict__ pos,
                             const float* __restrict__ mem,
                             float* __restrict__ X)
{
    int idx = blockIdx.x * 256 + threadIdx.x;
    if (idx >= S_TOT * DIM) return;
    int s = idx / DIM;
    int d = idx - s * DIM;
    if (s < MEMN) {
        X[idx] = mem[s * DIM + d];
    } else {
        int t = s - MEMN;
        X[idx] = emb[tokens[t] * DIM + d] + pos[t * DIM + d];
    }
}

// ---------------- layernorm stats (shared helper body) ---------------------
__device__ __forceinline__ void ln_stats(float v0, float v1, float v2,
                                         float& mean, float& inv)
{
    int t = threadIdx.x;
    float s = v0 + v1 + v2;
    float q = v0 * v0 + v1 * v1 + v2 * v2;
#pragma unroll
    for (int off = 16; off; off >>= 1) {
        s += __shfl_xor_sync(0xffffffffu, s, off);
        q += __shfl_xor_sync(0xffffffffu, q, off);
    }
    __shared__ float rs[8], rq[8];
    __shared__ float mean_sh, inv_sh;
    int w = t >> 5;
    if ((t & 31) == 0) { rs[w] = s; rq[w] = q; }
    __syncthreads();
    if (t == 0) {
        float S = 0.f, Q = 0.f;
#pragma unroll
        for (int i = 0; i < 8; i++) { S += rs[i]; Q += rq[i]; }
        float mn = S * (1.0f / DIM);
        float var = Q * (1.0f / DIM) - mn * mn;
        mean_sh = mn;
        inv_sh  = rsqrtf(var + 1e-5f);
    }
    __syncthreads();
    mean = mean_sh;
    inv  = inv_sh;
}

// LN -> fp32 (final output path)
__global__ void ln_kernel(const float* __restrict__ X,
                          const float* __restrict__ g,
                          const float* __restrict__ bt,
                          float* __restrict__ out,
                          int in_off)
{
    int row = blockIdx.x + in_off;
    const float* x = X + (size_t)row * DIM;
    int t = threadIdx.x;
    float v0 = x[t], v1 = x[t + 256], v2 = x[t + 512];
    float mean, inv;
    ln_stats(v0, v1, v2, mean, inv);
    float* o = out + (size_t)blockIdx.x * DIM;
    o[t]       = (v0 - mean) * inv * g[t]       + bt[t];
    o[t + 256] = (v1 - mean) * inv * g[t + 256] + bt[t + 256];
    o[t + 512] = (v2 - mean) * inv * g[t + 512] + bt[t + 512];
}

// LN -> bf16 hi/lo (GEMM input path)
__global__ void ln_hl_kernel(const float* __restrict__ X,
                             const float* __restrict__ g,
                             const float* __restrict__ bt,
                             __nv_bfloat16* __restrict__ oh,
                             __nv_bfloat16* __restrict__ ol)
{
    int row = blockIdx.x;
    const float* x = X + (size_t)row * DIM;
    int t = threadIdx.x;
    float v0 = x[t], v1 = x[t + 256], v2 = x[t + 512];
    float mean, inv;
    ln_stats(v0, v1, v2, mean, inv);
    size_t base = (size_t)row * DIM;
#pragma unroll
    for (int i = 0; i < 3; i++) {
        int c = t + i * 256;
        float v = (i == 0) ? v0 : (i == 1) ? v1 : v2;
        float y = (v - mean) * inv * g[c] + bt[c];
        __nv_bfloat16 h = __float2bfloat16(y);
        __nv_bfloat16 l = __float2bfloat16(y - __bfloat162float(h));
        oh[base + c] = h;
        ol[base + c] = l;
    }
}

// ---------------- gelu (tanh approximation) --------------------------------
__device__ __forceinline__ float gelu_tanh(float x)
{
    const float c = 0.7978845608028654f;
    float u = c * (x + 0.044715f * x * x * x);
    return 0.5f * x * (1.0f + tanhf(u));
}

// =================== bf16x3 tensor-core GEMM (pipelined) ====================
// C[m,n] = epi( A[m,:] . W[n,:] ), A/W given as preconverted bf16 hi/lo.
// BM=BN=128, BK=32, 8 warps (2x4), warp tile 64x32, 4-stage cp.async ring.
#define GPITCH 40
#define GMATB  10240                 // 128 rows x 40 elems x 2B
#define GSTAGEB (4 * GMATB)          // 40960
#define NSTAGE 4
#define GEMM_SMEM (NSTAGE * GSTAGEB) // 163840

template <bool GELU, bool RES, bool BIAS, bool OUTHL>
__global__ __launch_bounds__(256, 1)
void gemm_tc(const __nv_bfloat16* __restrict__ Ah, const __nv_bfloat16* __restrict__ Al,
             const __nv_bfloat16* __restrict__ Bh, const __nv_bfloat16* __restrict__ Bl,
             const float* __restrict__ bias, const float* __restrict__ resid,
             float* __restrict__ C,
             __nv_bfloat16* __restrict__ Oh, __nv_bfloat16* __restrict__ Ol,
             int Mr, int N, int K)
{
    extern __shared__ char smem[];
    const uint32_t sb = smem_u32(smem);
    const int tid = threadIdx.x, wid = tid >> 5, lane = tid & 31;
    const int bm = blockIdx.y, bn = blockIdx.x;
    const int wm = (wid >> 2) * 64;
    const int wn = (wid & 3) * 32;

    // loader mapping: this thread handles rows lrow and lrow+64, chunk kc (16B)
    const int lrow = tid >> 2;
    const int kc   = tid & 3;
    const int KT = K >> 5;

    float acc[4][4][4];
#pragma unroll
    for (int i = 0; i < 4; i++)
#pragma unroll
        for (int j = 0; j < 4; j++)
#pragma unroll
            for (int k = 0; k < 4; k++) acc[i][j][k] = 0.f;

    // stage issue: 8 cp.async.16B per thread
    auto issue = [&](int kt) {
        const uint32_t stg = sb + (kt % NSTAGE) * GSTAGEB;
        const int kb = kt * 32;
#pragma unroll
        for (int half = 0; half < 2; half++) {
            const int row = lrow + half * 64;
            const uint32_t d = stg + row * (GPITCH * 2) + kc * 16;
            int ga = bm * 128 + row;
            const bool av = ga < Mr;
            if (!av) ga = 0;
            const size_t aoff = (size_t)ga * K + kb + kc * 8;
            const size_t boff = (size_t)(bn * 128 + row) * K + kb + kc * 8;
            cp_async16(d,             Ah + aoff, av);
            cp_async16(d + GMATB,     Al + aoff, av);
            cp_async16(d + 2 * GMATB, Bh + boff, true);
            cp_async16(d + 3 * GMATB, Bl + boff, true);
        }
    };

#pragma unroll
    for (int p = 0; p < NSTAGE - 1; p++) { issue(p); CP_COMMIT(); }

    for (int kt = 0; kt < KT; kt++) {
        CP_WAIT2();
        __syncthreads();
        if (kt + NSTAGE - 1 < KT) { issue(kt + NSTAGE - 1); CP_COMMIT(); }

        const uint32_t base = sb + (kt % NSTAGE) * GSTAGEB;
#pragma unroll
        for (int ks = 0; ks < 2; ks++) {
            const int k0 = ks * 16;
            uint32_t aH[4][4], aL[4][4], bH[2][4], bL[2][4];
            const int arow = wm + (lane & 15);
            const int acol = k0 + ((lane >> 4) << 3);
#pragma unroll
            for (int mt = 0; mt < 4; mt++) {
                uint32_t ad = base + ((arow + mt * 16) * GPITCH + acol) * 2;
                ldsm_x4(aH[mt], ad);
                ldsm_x4(aL[mt], ad + GMATB);
            }
            const int brow = wn + (lane & 7) + ((lane >> 4) << 3);
            const int bcol = k0 + (((lane >> 3) & 1) << 3);
#pragma unroll
            for (int n2 = 0; n2 < 2; n2++) {
                uint32_t bd = base + 2 * GMATB + ((brow + n2 * 16) * GPITCH + bcol) * 2;
                ldsm_x4(bH[n2], bd);
                ldsm_x4(bL[n2], bd + GMATB);
            }
#pragma unroll
            for (int mt = 0; mt < 4; mt++)
#pragma unroll
                for (int nt = 0; nt < 4; nt++) {
                    const int n2 = nt >> 1, hb = (nt & 1) * 2;
                    mma16816(acc[mt][nt], aH[mt], bH[n2][hb], bH[n2][hb + 1]);
                    mma16816(acc[mt][nt], aH[mt], bL[n2][hb], bL[n2][hb + 1]);
                    mma16816(acc[mt][nt], aL[mt], bH[n2][hb], bH[n2][hb + 1]);
                }
        }
    }

    // ---- epilogue ----
#pragma unroll
    for (int mt = 0; mt < 4; mt++) {
        const int r0 = bm * 128 + wm + mt * 16 + (lane >> 2);
#pragma unroll
        for (int nt = 0; nt < 4; nt++) {
            const int col = bn * 128 + wn + nt * 8 + (lane & 3) * 2;
            float* c = acc[mt][nt];
            float bx = 0.f, by = 0.f;
            if (BIAS) { float2 bv = *(const float2*)(bias + col); bx = bv.x; by = bv.y; }
#pragma unroll
            for (int hh = 0; hh < 2; hh++) {
                const int r = r0 + hh * 8;
                if (r >= Mr) continue;
                float v0 = c[hh * 2 + 0], v1 = c[hh * 2 + 1];
                if (BIAS) { v0 += bx; v1 += by; }
                if (GELU) { v0 = gelu_tanh(v0); v1 = gelu_tanh(v1); }
                if (OUTHL) {
                    __nv_bfloat16 h0 = __float2bfloat16(v0);
                    __nv_bfloat16 h1 = __float2bfloat16(v1);
                    __nv_bfloat16 l0 = __float2bfloat16(v0 - __bfloat162float(h0));
                    __nv_bfloat16 l1 = __float2bfloat16(v1 - __bfloat162float(h1));
                    __nv_bfloat162 hv; hv.x = h0; hv.y = h1;
                    __nv_bfloat162 lv; lv.x = l0; lv.y = l1;
                    *(__nv_bfloat162*)(Oh + (size_t)r * N + col) = hv;
                    *(__nv_bfloat162*)(Ol + (size_t)r * N + col) = lv;
                } else {
                    if (RES) {
                        float2 rv = *(const float2*)(resid + (size_t)r * N + col);
                        v0 += rv.x; v1 += rv.y;
                    }
                    *(float2*)(C + (size_t)r * N + col) = make_float2(v0, v1);
                }
            }
        }
    }
}

// ---------------- flash attention (causal), one head x 64-query block ------
#define KPAD 68
__global__ __launch_bounds__(256)
void attn_kernel(const float* __restrict__ Q, const float* __restrict__ K,
                 const float* __restrict__ V,
                 __nv_bfloat16* __restrict__ Oh, __nv_bfloat16* __restrict__ Ol)
{
    extern __shared__ float sm[];
    float* Qs = sm;
    float* Ks = Qs + 64 * 64;
    float* Vs = Ks + 64 * KPAD;
    float* Ps = Vs + 64 * KPAD;

    const int qb = blockIdx.x, h = blockIdx.y;
    const int t  = threadIdx.x;
    const int tx = t & 15, ty = t >> 4;
    const int lrow = t >> 2;
    const int lcg  = (t & 3) * 16;

    {
        const float4* s4 = (const float4*)(Q + (size_t)(qb * 64 + lrow) * DIM + h * HD + lcg);
        float4* dq = (float4*)(Qs + lrow * 64 + lcg);
        dq[0] = s4[0]; dq[1] = s4[1]; dq[2] = s4[2]; dq[3] = s4[3];
    }

    float m[4], l[4], o[4][4];
#pragma unroll
    for (int i = 0; i < 4; i++) {
        m[i] = -1e30f; l[i] = 0.f;
#pragma unroll
        for (int j = 0; j < 4; j++) o[i][j] = 0.f;
    }
    const float scale = 0.125f;

    for (int kb = 0; kb <= qb; kb++) {
        __syncthreads();
        {
            const float4* ks = (const float4*)(K + (size_t)(kb * 64 + lrow) * DIM + h * HD + lcg);
            const float4* vs = (const float4*)(V + (size_t)(kb * 64 + lrow) * DIM + h * HD + lcg);
            float4* kd = (float4*)(Ks + lrow * KPAD + lcg);
            float4* vd = (float4*)(Vs + lrow * KPAD + lcg);
#pragma unroll
            for (int i = 0; i < 4; i++) { kd[i] = ks[i]; vd[i] = vs[i]; }
        }
        __syncthreads();

        float sv[4][4];
#pragma unroll
        for (int i = 0; i < 4; i++)
#pragma unroll
            for (int j = 0; j < 4; j++) sv[i][j] = 0.f;
#pragma unroll 4
        for (int k = 0; k < 64; k += 4) {
            float4 qa[4], kb4[4];
#pragma unroll
            for (int i = 0; i < 4; i++) qa[i]  = *(const float4*)(Qs + (ty * 4 + i) * 64 + k);
#pragma unroll
            for (int j = 0; j < 4; j++) kb4[j] = *(const float4*)(Ks + (tx * 4 + j) * KPAD + k);
#pragma unroll
            for (int i = 0; i < 4; i++)
#pragma unroll
                for (int j = 0; j < 4; j++)
                    sv[i][j] += qa[i].x * kb4[j].x + qa[i].y * kb4[j].y +
                                qa[i].z * kb4[j].z + qa[i].w * kb4[j].w;
        }

#pragma unroll
        for (int i = 0; i < 4; i++)
#pragma unroll
            for (int j = 0; j < 4; j++) {
                float s = sv[i][j] * scale;
                if (kb == qb && (tx * 4 + j) > (ty * 4 + i)) s = -1e30f;
                sv[i][j] = s;
            }

#pragma unroll
        for (int i = 0; i < 4; i++) {
            float lm = fmaxf(fmaxf(sv[i][0], sv[i][1]), fmaxf(sv[i][2], sv[i][3]));
#pragma unroll
            for (int off = 1; off < 16; off <<= 1)
                lm = fmaxf(lm, __shfl_xor_sync(0xffffffffu, lm, off));
            float mn   = fmaxf(m[i], lm);
            float corr = __expf(m[i] - mn);
            float ls = 0.f;
#pragma unroll
            for (int j = 0; j < 4; j++) {
                float p = __expf(sv[i][j] - mn);
                sv[i][j] = p;
                ls += p;
            }
#pragma unroll
            for (int off = 1; off < 16; off <<= 1)
                ls += __shfl_xor_sync(0xffffffffu, ls, off);
            l[i] = l[i] * corr + ls;
            m[i] = mn;
#pragma unroll
            for (int j = 0; j < 4; j++) o[i][j] *= corr;
            *(float4*)(Ps + (ty * 4 + i) * KPAD + tx * 4) =
                make_float4(sv[i][0], sv[i][1], sv[i][2], sv[i][3]);
        }
        __syncthreads();

#pragma unroll 4
        for (int j = 0; j < 64; j++) {
            float4 v4 = *(const float4*)(Vs + j * KPAD + tx * 4);
#pragma unroll
            for (int i = 0; i < 4; i++) {
                float p = Ps[(ty * 4 + i) * KPAD + j];
                o[i][0] = fmaf(p, v4.x, o[i][0]);
                o[i][1] = fmaf(p, v4.y, o[i][1]);
                o[i][2] = fmaf(p, v4.z, o[i][2]);
                o[i][3] = fmaf(p, v4.w, o[i][3]);
            }
        }
    }

#pragma unroll
    for (int i = 0; i < 4; i++) {
        float inv = 1.0f / l[i];
        size_t rbase = (size_t)(qb * 64 + ty * 4 + i) * DIM + h * HD + tx * 4;
#pragma unroll
        for (int j = 0; j < 4; j++) {
            float y = o[i][j] * inv;
            __nv_bfloat16 hh = __float2bfloat16(y);
            Oh[rbase + j] = hh;
            Ol[rbase + j] = __float2bfloat16(y - __bfloat162float(hh));
        }
    }
}

// ---------------- launch ----------------------------------------------------
extern "C" void kernel_launch(void* const* d_in, const int* in_sizes, int n_in,
                              void* d_out, int out_size)
{
    const int*   tokens = (const int*)  d_in[0];
    const float* emb    = (const float*)d_in[1];
    const float* pos    = (const float*)d_in[2];
    const float* mem    = (const float*)d_in[3];
    const float* ln1_s  = (const float*)d_in[4];
    const float* ln1_b  = (const float*)d_in[5];
    const float* wq     = (const float*)d_in[6];
    const float* wk     = (const float*)d_in[7];
    const float* wv     = (const float*)d_in[8];
    const float* wo     = (const float*)d_in[9];
    const float* ln2_s  = (const float*)d_in[10];
    const float* ln2_b  = (const float*)d_in[11];
    const float* w1     = (const float*)d_in[12];
    const float* b1     = (const float*)d_in[13];
    const float* w2     = (const float*)d_in[14];
    const float* b2     = (const float*)d_in[15];
    const float* lnm_s  = (const float*)d_in[16];
    const float* lnm_b  = (const float*)d_in[17];

    float *X, *Q, *Kb, *Vb;
    __nv_bfloat16 *Nh, *Nl, *Aoh, *Aol, *Fh, *Fl, *Wh, *Wl;
    cudaGetSymbolAddress((void**)&X,   g_X);
    cudaGetSymbolAddress((void**)&Q,   g_Q);
    cudaGetSymbolAddress((void**)&Kb,  g_K);
    cudaGetSymbolAddress((void**)&Vb,  g_V);
    cudaGetSymbolAddress((void**)&Nh,  g_Nh);
    cudaGetSymbolAddress((void**)&Nl,  g_Nl);
    cudaGetSymbolAddress((void**)&Aoh, g_Ahp);
    cudaGetSymbolAddress((void**)&Aol, g_Alp);
    cudaGetSymbolAddress((void**)&Fh,  g_Fh);
    cudaGetSymbolAddress((void**)&Fl,  g_Fl);
    cudaGetSymbolAddress((void**)&Wh,  g_Wh);
    cudaGetSymbolAddress((void**)&Wl,  g_Wl);

    const int ATTN_SMEM = (64 * 64 + 3 * 64 * KPAD) * (int)sizeof(float);
    cudaFuncSetAttribute(attn_kernel, cudaFuncAttributeMaxDynamicSharedMemorySize, ATTN_SMEM);
    cudaFuncSetAttribute(gemm_tc<false, false, false, false>, cudaFuncAttributeMaxDynamicSharedMemorySize, GEMM_SMEM);
    cudaFuncSetAttribute(gemm_tc<false, true,  false, false>, cudaFuncAttributeMaxDynamicSharedMemorySize, GEMM_SMEM);
    cudaFuncSetAttribute(gemm_tc<true,  false, true,  true >, cudaFuncAttributeMaxDynamicSharedMemorySize, GEMM_SMEM);
    cudaFuncSetAttribute(gemm_tc<false, true,  true,  false>, cudaFuncAttributeMaxDynamicSharedMemorySize, GEMM_SMEM);

    // ---- weight pre-conversion (fp32 -> bf16 hi/lo) ----
    {
        const int np = WSZ_P / 4, nf = WSZ_FF / 4;
        conv_hl_kernel<<<(np + 255) / 256, 256>>>(wq, Wh + OFF_WQ, Wl + OFF_WQ, np);
        conv_hl_kernel<<<(np + 255) / 256, 256>>>(wk, Wh + OFF_WK, Wl + OFF_WK, np);
        conv_hl_kernel<<<(np + 255) / 256, 256>>>(wv, Wh + OFF_WV, Wl + OFF_WV, np);
        conv_hl_kernel<<<(np + 255) / 256, 256>>>(wo, Wh + OFF_WO, Wl + OFF_WO, np);
        conv_hl_kernel<<<(nf + 255) / 256, 256>>>(w1, Wh + OFF_W1, Wl + OFF_W1, nf);
        conv_hl_kernel<<<(nf + 255) / 256, 256>>>(w2, Wh + OFF_W2, Wl + OFF_W2, nf);
    }

    embed_kernel<<<(S_TOT * DIM + 255) / 256, 256>>>(tokens, emb, pos, mem, X);

    const dim3 gProj(DIM / 128, (S_TOT + 127) / 128);   // (6, 17)
    const dim3 gFF1 (HID / 128, (S_TOT + 127) / 128);   // (24, 17)

    for (int l = 0; l < NLAYER; l++) {
        ln_hl_kernel<<<S_TOT, 256>>>(X, ln1_s + l * DIM, ln1_b + l * DIM, Nh, Nl);

        gemm_tc<false, false, false, false><<<gProj, 256, GEMM_SMEM>>>(
            Nh, Nl, Wh + OFF_WQ + (size_t)l * DIM * DIM, Wl + OFF_WQ + (size_t)l * DIM * DIM,
            nullptr, nullptr, Q, nullptr, nullptr, S_TOT, DIM, DIM);
        gemm_tc<false, false, false, false><<<gProj, 256, GEMM_SMEM>>>(
            Nh, Nl, Wh + OFF_WK + (size_t)l * DIM * DIM, Wl + OFF_WK + (size_t)l * DIM * DIM,
            nullptr, nullptr, Kb, nullptr, nullptr, S_TOT, DIM, DIM);
        gemm_tc<false, false, false, false><<<gProj, 256, GEMM_SMEM>>>(
            Nh, Nl, Wh + OFF_WV + (size_t)l * DIM * DIM, Wl + OFF_WV + (size_t)l * DIM * DIM,
            nullptr, nullptr, Vb, nullptr, nullptr, S_TOT, DIM, DIM);

        attn_kernel<<<dim3(S_TOT / 64, NHEAD), 256, ATTN_SMEM>>>(Q, Kb, Vb, Aoh, Aol);

        gemm_tc<false, true, false, false><<<gProj, 256, GEMM_SMEM>>>(
            Aoh, Aol, Wh + OFF_WO + (size_t)l * DIM * DIM, Wl + OFF_WO + (size_t)l * DIM * DIM,
            nullptr, X, X, nullptr, nullptr, S_TOT, DIM, DIM);

        ln_hl_kernel<<<S_TOT, 256>>>(X, ln2_s + l * DIM, ln2_b + l * DIM, Nh, Nl);

        gemm_tc<true, false, true, true><<<gFF1, 256, GEMM_SMEM>>>(
            Nh, Nl, Wh + OFF_W1 + (size_t)l * HID * DIM, Wl + OFF_W1 + (size_t)l * HID * DIM,
            b1 + l * HID, nullptr, nullptr, Fh, Fl, S_TOT, HID, DIM);
        gemm_tc<false, true, true, false><<<gProj, 256, GEMM_SMEM>>>(
            Fh, Fl, Wh + OFF_W2 + (size_t)l * DIM * HID, Wl + OFF_W2 + (size_t)l * DIM * HID,
            b2 + l * DIM, X, X, nullptr, nullptr, S_TOT, DIM, HID);
    }

    ln_kernel<<<MEMN, 256>>>(X, lnm_s, lnm_b, (float*)d_out, S_TOT - MEMN);
}

// round 5
// speedup vs baseline: 3.5413x; 1.9257x over previous
#include <cuda_runtime.h>
#include <cuda_bf16.h>
#include <cstdint>

#define S_TOT 2112          // 64 mem + 2048 tokens
#define MEMN  64
#define DIM   768
#define HID   3072
#define NHEAD 12
#define HD    64
#define NLAYER 4
#define QKVN  (3 * DIM)     // 2304

// ---------------- scratch (device globals; no allocation allowed) ----------
__device__ __align__(16) float g_X [S_TOT * DIM];

__device__ __align__(16) __nv_bfloat16 g_Nh[S_TOT * DIM];
__device__ __align__(16) __nv_bfloat16 g_Nl[S_TOT * DIM];
__device__ __align__(16) __nv_bfloat16 g_QKVh[S_TOT * QKVN];
__device__ __align__(16) __nv_bfloat16 g_QKVl[S_TOT * QKVN];
__device__ __align__(16) __nv_bfloat16 g_Ahp[S_TOT * DIM];
__device__ __align__(16) __nv_bfloat16 g_Alp[S_TOT * DIM];
__device__ __align__(16) __nv_bfloat16 g_Fh[S_TOT * HID];
__device__ __align__(16) __nv_bfloat16 g_Fl[S_TOT * HID];

// preconverted weights (hi/lo bf16), all layers
#define WSZ_P   (NLAYER * DIM * DIM)
#define WSZ_FF  (NLAYER * HID * DIM)
#define OFF_QKV 0
#define OFF_WO  (OFF_QKV + 3 * WSZ_P)
#define OFF_W1  (OFF_WO + WSZ_P)
#define OFF_W2  (OFF_W1 + WSZ_FF)
#define WTOT    (OFF_W2 + WSZ_FF)
__device__ __align__(16) __nv_bfloat16 g_Wh[WTOT];
__device__ __align__(16) __nv_bfloat16 g_Wl[WTOT];

// =================== helpers ================================================
__device__ __forceinline__ uint32_t smem_u32(const void* p) {
    uint32_t a;
    asm("{ .reg .u64 t; cvta.to.shared.u64 t, %1; cvt.u32.u64 %0, t; }"
        : "=r"(a) : "l"(p));
    return a;
}
__device__ __forceinline__ void ldsm_x4(uint32_t* r, uint32_t addr) {
    asm volatile("ldmatrix.sync.aligned.m8n8.x4.shared.b16 {%0,%1,%2,%3}, [%4];"
                 : "=r"(r[0]), "=r"(r[1]), "=r"(r[2]), "=r"(r[3]) : "r"(addr));
}
__device__ __forceinline__ void ldsm_x4t(uint32_t* r, uint32_t addr) {
    asm volatile("ldmatrix.sync.aligned.m8n8.x4.trans.shared.b16 {%0,%1,%2,%3}, [%4];"
                 : "=r"(r[0]), "=r"(r[1]), "=r"(r[2]), "=r"(r[3]) : "r"(addr));
}
__device__ __forceinline__ void mma16816(float* c, const uint32_t* a,
                                         const uint32_t b0, const uint32_t b1) {
    asm volatile("mma.sync.aligned.m16n8k16.row.col.f32.bf16.bf16.f32 "
                 "{%0,%1,%2,%3}, {%4,%5,%6,%7}, {%8,%9}, {%0,%1,%2,%3};"
                 : "+f"(c[0]), "+f"(c[1]), "+f"(c[2]), "+f"(c[3])
                 : "r"(a[0]), "r"(a[1]), "r"(a[2]), "r"(a[3]), "r"(b0), "r"(b1));
}
__device__ __forceinline__ void cp_async16(uint32_t dst, const void* src, bool pred) {
    int sz = pred ? 16 : 0;
    asm volatile("cp.async.cg.shared.global [%0], [%1], 16, %2;"
                 :: "r"(dst), "l"(src), "r"(sz) : "memory");
}
#define CP_COMMIT() asm volatile("cp.async.commit_group;" ::: "memory")
#define CP_WAIT2()  asm volatile("cp.async.wait_group 2;" ::: "memory")
#define CP_WAIT0()  asm volatile("cp.async.wait_group 0;" ::: "memory")

__device__ __forceinline__ void split4(float4 v, uint2& hi, uint2& lo)
{
    __nv_bfloat16 h0 = __float2bfloat16(v.x);
    __nv_bfloat16 h1 = __float2bfloat16(v.y);
    __nv_bfloat16 h2 = __float2bfloat16(v.z);
    __nv_bfloat16 h3 = __float2bfloat16(v.w);
    __nv_bfloat16 l0 = __float2bfloat16(v.x - __bfloat162float(h0));
    __nv_bfloat16 l1 = __float2bfloat16(v.y - __bfloat162float(h1));
    __nv_bfloat16 l2 = __float2bfloat16(v.z - __bfloat162float(h2));
    __nv_bfloat16 l3 = __float2bfloat16(v.w - __bfloat162float(h3));
    hi.x = (uint32_t)__bfloat16_as_ushort(h1) << 16 | __bfloat16_as_ushort(h0);
    hi.y = (uint32_t)__bfloat16_as_ushort(h3) << 16 | __bfloat16_as_ushort(h2);
    lo.x = (uint32_t)__bfloat16_as_ushort(l1) << 16 | __bfloat16_as_ushort(l0);
    lo.y = (uint32_t)__bfloat16_as_ushort(l3) << 16 | __bfloat16_as_ushort(l2);
}
__device__ __forceinline__ void split2(float a, float b, uint32_t& hi, uint32_t& lo)
{
    __nv_bfloat16 ha = __float2bfloat16(a), hb = __float2bfloat16(b);
    __nv_bfloat16 la = __float2bfloat16(a - __bfloat162float(ha));
    __nv_bfloat16 lb = __float2bfloat16(b - __bfloat162float(hb));
    hi = (uint32_t)__bfloat16_as_ushort(hb) << 16 | __bfloat16_as_ushort(ha);
    lo = (uint32_t)__bfloat16_as_ushort(lb) << 16 | __bfloat16_as_ushort(la);
}

// ---------------- weight pre-conversion ------------------------------------
__global__ void conv_hl_kernel(const float* __restrict__ s,
                               __nv_bfloat16* __restrict__ dh,
                               __nv_bfloat16* __restrict__ dl, int n4)
{
    int i = blockIdx.x * 256 + threadIdx.x;
    if (i >= n4) return;
    float4 v = ((const float4*)s)[i];
    uint2 hi, lo;
    split4(v, hi, lo);
    ((uint2*)dh)[i] = hi;
    ((uint2*)dl)[i] = lo;
}
// QKV pack: src [L][768][768] -> dst layer block stride 3*768*768 (dst pre-offset by tensor)
__global__ void conv_hl_qkv(const float* __restrict__ s,
                            __nv_bfloat16* __restrict__ dh,
                            __nv_bfloat16* __restrict__ dl)
{
    const int n4l = DIM * DIM / 4;
    int i = blockIdx.x * 256 + threadIdx.x;
    if (i >= n4l * NLAYER) return;
    int l = i / n4l, r = i - l * n4l;
    float4 v = ((const float4*)s)[i];
    uint2 hi, lo;
    split4(v, hi, lo);
    int o = l * (3 * DIM * DIM / 4) + r;
    ((uint2*)dh)[o] = hi;
    ((uint2*)dl)[o] = lo;
}

// ---------------- embedding ------------------------------------------------
__global__ void embed_kernel(const int* __restrict__ tokens,
                             const float* __restrict__ emb,
                             const float* __restrict__ pos,
                             const float* __restrict__ mem,
                             float* __restrict__ X)
{
    int idx = blockIdx.x * 256 + threadIdx.x;
    if (idx >= S_TOT * DIM) return;
    int s = idx / DIM;
    int d = idx - s * DIM;
    if (s < MEMN) {
        X[idx] = mem[s * DIM + d];
    } else {
        int t = s - MEMN;
        X[idx] = emb[tokens[t] * DIM + d] + pos[t * DIM + d];
    }
}

// ---------------- layernorm ------------------------------------------------
__device__ __forceinline__ void ln_stats(float v0, float v1, float v2,
                                         float& mean, float& inv)
{
    int t = threadIdx.x;
    float s = v0 + v1 + v2;
    float q = v0 * v0 + v1 * v1 + v2 * v2;
#pragma unroll
    for (int off = 16; off; off >>= 1) {
        s += __shfl_xor_sync(0xffffffffu, s, off);
        q += __shfl_xor_sync(0xffffffffu, q, off);
    }
    __shared__ float rs[8], rq[8];
    __shared__ float mean_sh, inv_sh;
    int w = t >> 5;
    if ((t & 31) == 0) { rs[w] = s; rq[w] = q; }
    __syncthreads();
    if (t == 0) {
        float S = 0.f, Q = 0.f;
#pragma unroll
        for (int i = 0; i < 8; i++) { S += rs[i]; Q += rq[i]; }
        float mn = S * (1.0f / DIM);
        float var = Q * (1.0f / DIM) - mn * mn;
        mean_sh = mn;
        inv_sh  = rsqrtf(var + 1e-5f);
    }
    __syncthreads();
    mean = mean_sh;
    inv  = inv_sh;
}

__global__ void ln_kernel(const float* __restrict__ X,
                          const float* __restrict__ g,
                          const float* __restrict__ bt,
                          float* __restrict__ out, int in_off)
{
    int row = blockIdx.x + in_off;
    const float* x = X + (size_t)row * DIM;
    int t = threadIdx.x;
    float v0 = x[t], v1 = x[t + 256], v2 = x[t + 512];
    float mean, inv;
    ln_stats(v0, v1, v2, mean, inv);
    float* o = out + (size_t)blockIdx.x * DIM;
    o[t]       = (v0 - mean) * inv * g[t]       + bt[t];
    o[t + 256] = (v1 - mean) * inv * g[t + 256] + bt[t + 256];
    o[t + 512] = (v2 - mean) * inv * g[t + 512] + bt[t + 512];
}

__global__ void ln_hl_kernel(const float* __restrict__ X,
                             const float* __restrict__ g,
                             const float* __restrict__ bt,
                             __nv_bfloat16* __restrict__ oh,
                             __nv_bfloat16* __restrict__ ol)
{
    int row = blockIdx.x;
    const float* x = X + (size_t)row * DIM;
    int t = threadIdx.x;
    float v0 = x[t], v1 = x[t + 256], v2 = x[t + 512];
    float mean, inv;
    ln_stats(v0, v1, v2, mean, inv);
    size_t base = (size_t)row * DIM;
#pragma unroll
    for (int i = 0; i < 3; i++) {
        int c = t + i * 256;
        float v = (i == 0) ? v0 : (i == 1) ? v1 : v2;
        float y = (v - mean) * inv * g[c] + bt[c];
        __nv_bfloat16 h = __float2bfloat16(y);
        oh[base + c] = h;
        ol[base + c] = __float2bfloat16(y - __bfloat162float(h));
    }
}

__device__ __forceinline__ float gelu_tanh(float x)
{
    const float c = 0.7978845608028654f;
    float u = c * (x + 0.044715f * x * x * x);
    return 0.5f * x * (1.0f + tanhf(u));
}

// =================== bf16x3 tensor-core GEMM (pipelined) ====================
#define GPITCH 40
#define GMATB  10240
#define GSTAGEB (4 * GMATB)
#define NSTAGE 4
#define GEMM_SMEM (NSTAGE * GSTAGEB)

template <bool GELU, bool RES, bool BIAS, bool OUTHL>
__global__ __launch_bounds__(256, 1)
void gemm_tc(const __nv_bfloat16* __restrict__ Ah, const __nv_bfloat16* __restrict__ Al,
             const __nv_bfloat16* __restrict__ Bh, const __nv_bfloat16* __restrict__ Bl,
             const float* __restrict__ bias, const float* __restrict__ resid,
             float* __restrict__ C,
             __nv_bfloat16* __restrict__ Oh, __nv_bfloat16* __restrict__ Ol,
             int Mr, int N, int K)
{
    extern __shared__ char smem[];
    const uint32_t sb = smem_u32(smem);
    const int tid = threadIdx.x, wid = tid >> 5, lane = tid & 31;
    const int bm = blockIdx.y, bn = blockIdx.x;
    const int wm = (wid >> 2) * 64;
    const int wn = (wid & 3) * 32;

    const int lrow = tid >> 2;
    const int kc   = tid & 3;
    const int KT = K >> 5;

    float acc[4][4][4];
#pragma unroll
    for (int i = 0; i < 4; i++)
#pragma unroll
        for (int j = 0; j < 4; j++)
#pragma unroll
            for (int k = 0; k < 4; k++) acc[i][j][k] = 0.f;

    auto issue = [&](int kt) {
        const uint32_t stg = sb + (kt % NSTAGE) * GSTAGEB;
        const int kb = kt * 32;
#pragma unroll
        for (int half = 0; half < 2; half++) {
            const int row = lrow + half * 64;
            const uint32_t d = stg + row * (GPITCH * 2) + kc * 16;
            int ga = bm * 128 + row;
            const bool av = ga < Mr;
            if (!av) ga = 0;
            const size_t aoff = (size_t)ga * K + kb + kc * 8;
            const size_t boff = (size_t)(bn * 128 + row) * K + kb + kc * 8;
            cp_async16(d,             Ah + aoff, av);
            cp_async16(d + GMATB,     Al + aoff, av);
            cp_async16(d + 2 * GMATB, Bh + boff, true);
            cp_async16(d + 3 * GMATB, Bl + boff, true);
        }
    };

#pragma unroll
    for (int p = 0; p < NSTAGE - 1; p++) { issue(p); CP_COMMIT(); }

    for (int kt = 0; kt < KT; kt++) {
        CP_WAIT2();
        __syncthreads();
        if (kt + NSTAGE - 1 < KT) { issue(kt + NSTAGE - 1); CP_COMMIT(); }

        const uint32_t base = sb + (kt % NSTAGE) * GSTAGEB;
#pragma unroll
        for (int ks = 0; ks < 2; ks++) {
            const int k0 = ks * 16;
            uint32_t aH[4][4], aL[4][4], bH[2][4], bL[2][4];
            const int arow = wm + (lane & 15);
            const int acol = k0 + ((lane >> 4) << 3);
#pragma unroll
            for (int mt = 0; mt < 4; mt++) {
                uint32_t ad = base + ((arow + mt * 16) * GPITCH + acol) * 2;
                ldsm_x4(aH[mt], ad);
                ldsm_x4(aL[mt], ad + GMATB);
            }
            const int brow = wn + (lane & 7) + ((lane >> 4) << 3);
            const int bcol = k0 + (((lane >> 3) & 1) << 3);
#pragma unroll
            for (int n2 = 0; n2 < 2; n2++) {
                uint32_t bd = base + 2 * GMATB + ((brow + n2 * 16) * GPITCH + bcol) * 2;
                ldsm_x4(bH[n2], bd);
                ldsm_x4(bL[n2], bd + GMATB);
            }
#pragma unroll
            for (int mt = 0; mt < 4; mt++)
#pragma unroll
                for (int nt = 0; nt < 4; nt++) {
                    const int n2 = nt >> 1, hb = (nt & 1) * 2;
                    mma16816(acc[mt][nt], aH[mt], bH[n2][hb], bH[n2][hb + 1]);
                    mma16816(acc[mt][nt], aH[mt], bL[n2][hb], bL[n2][hb + 1]);
                    mma16816(acc[mt][nt], aL[mt], bH[n2][hb], bH[n2][hb + 1]);
                }
        }
    }

#pragma unroll
    for (int mt = 0; mt < 4; mt++) {
        const int r0 = bm * 128 + wm + mt * 16 + (lane >> 2);
#pragma unroll
        for (int nt = 0; nt < 4; nt++) {
            const int col = bn * 128 + wn + nt * 8 + (lane & 3) * 2;
            float* c = acc[mt][nt];
            float bx = 0.f, by = 0.f;
            if (BIAS) { float2 bv = *(const float2*)(bias + col); bx = bv.x; by = bv.y; }
#pragma unroll
            for (int hh = 0; hh < 2; hh++) {
                const int r = r0 + hh * 8;
                if (r >= Mr) continue;
                float v0 = c[hh * 2 + 0], v1 = c[hh * 2 + 1];
                if (BIAS) { v0 += bx; v1 += by; }
                if (GELU) { v0 = gelu_tanh(v0); v1 = gelu_tanh(v1); }
                if (OUTHL) {
                    uint32_t hi, lo;
                    split2(v0, v1, hi, lo);
                    *(uint32_t*)(Oh + (size_t)r * N + col) = hi;
                    *(uint32_t*)(Ol + (size_t)r * N + col) = lo;
                } else {
                    if (RES) {
                        float2 rv = *(const float2*)(resid + (size_t)r * N + col);
                        v0 += rv.x; v1 += rv.y;
                    }
                    *(float2*)(C + (size_t)r * N + col) = make_float2(v0, v1);
                }
            }
        }
    }
}

// =================== tensor-core flash attention ============================
// 4 warps / block; block = (qb: 64 queries, h: head). bf16x3 QK and PV.
// smem: Qh Ql Kh Kl Vh Vl, each 64 x 72(pitch) bf16 = 9216 B; total 55296 B.
#define APITCH 72
#define AMATB  9216
#define ATTN_SMEM (6 * AMATB)

__global__ __launch_bounds__(128)
void attn_tc(const __nv_bfloat16* __restrict__ QKVh,
             const __nv_bfloat16* __restrict__ QKVl,
             __nv_bfloat16* __restrict__ Oh, __nv_bfloat16* __restrict__ Ol)
{
    extern __shared__ char asmem[];
    const uint32_t sb = smem_u32(asmem);
    const uint32_t oQh = 0, oQl = AMATB, oKh = 2 * AMATB, oKl = 3 * AMATB,
                   oVh = 4 * AMATB, oVl = 5 * AMATB;
    const int qb = blockIdx.x, h = blockIdx.y;
    const int tid = threadIdx.x, wid = tid >> 5, lane = tid & 31;
    const int wr = wid * 16;

    // load Q hi/lo (once)
#pragma unroll
    for (int i = 0; i < 4; i++) {
        int idx = tid + i * 128;
        int row = idx >> 3, ch = idx & 7;
        size_t goff = (size_t)(qb * 64 + row) * QKVN + h * HD + ch * 8;
        uint32_t soff = row * (APITCH * 2) + ch * 16;
        cp_async16(sb + oQh + soff, QKVh + goff, true);
        cp_async16(sb + oQl + soff, QKVl + goff, true);
    }
    CP_COMMIT();

    float m_[2] = {-1e30f, -1e30f}, l_[2] = {0.f, 0.f};
    float ov[8][4];
#pragma unroll
    for (int i = 0; i < 8; i++)
#pragma unroll
        for (int j = 0; j < 4; j++) ov[i][j] = 0.f;
    const float scale = 0.125f;

    for (int kb = 0; kb <= qb; kb++) {
        __syncthreads();     // previous iteration's reads done
#pragma unroll
        for (int i = 0; i < 4; i++) {
            int idx = tid + i * 128;
            int row = idx >> 3, ch = idx & 7;
            size_t gK = (size_t)(kb * 64 + row) * QKVN + DIM + h * HD + ch * 8;
            size_t gV = (size_t)(kb * 64 + row) * QKVN + 2 * DIM + h * HD + ch * 8;
            uint32_t soff = row * (APITCH * 2) + ch * 16;
            cp_async16(sb + oKh + soff, QKVh + gK, true);
            cp_async16(sb + oKl + soff, QKVl + gK, true);
            cp_async16(sb + oVh + soff, QKVh + gV, true);
            cp_async16(sb + oVl + soff, QKVl + gV, true);
        }
        CP_COMMIT();
        CP_WAIT0();
        __syncthreads();

        // ---- S = Q K^T (bf16x3) ----
        float sv[8][4];
#pragma unroll
        for (int i = 0; i < 8; i++)
#pragma unroll
            for (int j = 0; j < 4; j++) sv[i][j] = 0.f;

        const int ar = wr + (lane & 15);
        const int ac = (lane >> 4) << 3;
        const int br = (lane & 7) + ((lane >> 4) << 3);
        const int bc = ((lane >> 3) & 1) << 3;
#pragma unroll
        for (int ks = 0; ks < 4; ks++) {
            uint32_t aH[4], aL[4];
            uint32_t ao = sb + (ar * APITCH + ks * 16 + ac) * 2;
            ldsm_x4(aH, ao + oQh);
            ldsm_x4(aL, ao + oQl);
#pragma unroll
            for (int g = 0; g < 4; g++) {
                uint32_t bH4[4], bL4[4];
                uint32_t bo = sb + ((g * 16 + br) * APITCH + ks * 16 + bc) * 2;
                ldsm_x4(bH4, bo + oKh);
                ldsm_x4(bL4, bo + oKl);
                mma16816(sv[2 * g],     aH, bH4[0], bH4[1]);
                mma16816(sv[2 * g],     aH, bL4[0], bL4[1]);
                mma16816(sv[2 * g],     aL, bH4[0], bH4[1]);
                mma16816(sv[2 * g + 1], aH, bH4[2], bH4[3]);
                mma16816(sv[2 * g + 1], aH, bL4[2], bL4[3]);
                mma16816(sv[2 * g + 1], aL, bH4[2], bH4[3]);
            }
        }

        // ---- scale + causal mask ----
        const int lr0 = lane >> 2;             // local row (warp-relative)
        const int lc0 = (lane & 3) * 2;
#pragma unroll
        for (int nt = 0; nt < 8; nt++)
#pragma unroll
            for (int e = 0; e < 4; e++) {
                float x = sv[nt][e] * scale;
                if (kb == qb) {
                    int kcol = nt * 8 + lc0 + (e & 1);
                    int qrow = wr + lr0 + ((e >> 1) << 3);
                    if (kcol > qrow) x = -1e30f;
                }
                sv[nt][e] = x;
            }

        // ---- online softmax (rows lr0, lr0+8) ----
        float mx0 = -1e30f, mx1 = -1e30f;
#pragma unroll
        for (int nt = 0; nt < 8; nt++) {
            mx0 = fmaxf(mx0, fmaxf(sv[nt][0], sv[nt][1]));
            mx1 = fmaxf(mx1, fmaxf(sv[nt][2], sv[nt][3]));
        }
        mx0 = fmaxf(mx0, __shfl_xor_sync(0xffffffffu, mx0, 1));
        mx0 = fmaxf(mx0, __shfl_xor_sync(0xffffffffu, mx0, 2));
        mx1 = fmaxf(mx1, __shfl_xor_sync(0xffffffffu, mx1, 1));
        mx1 = fmaxf(mx1, __shfl_xor_sync(0xffffffffu, mx1, 2));
        float mn0 = fmaxf(m_[0], mx0), mn1 = fmaxf(m_[1], mx1);
        float cr0 = __expf(m_[0] - mn0), cr1 = __expf(m_[1] - mn1);
        float sum0 = 0.f, sum1 = 0.f;
#pragma unroll
        for (int nt = 0; nt < 8; nt++) {
            float p0 = __expf(sv[nt][0] - mn0);
            float p1 = __expf(sv[nt][1] - mn0);
            float p2 = __expf(sv[nt][2] - mn1);
            float p3 = __expf(sv[nt][3] - mn1);
            sv[nt][0] = p0; sv[nt][1] = p1; sv[nt][2] = p2; sv[nt][3] = p3;
            sum0 += p0 + p1;
            sum1 += p2 + p3;
        }
        sum0 += __shfl_xor_sync(0xffffffffu, sum0, 1);
        sum0 += __shfl_xor_sync(0xffffffffu, sum0, 2);
        sum1 += __shfl_xor_sync(0xffffffffu, sum1, 1);
        sum1 += __shfl_xor_sync(0xffffffffu, sum1, 2);
        l_[0] = l_[0] * cr0 + sum0;
        l_[1] = l_[1] * cr1 + sum1;
        m_[0] = mn0; m_[1] = mn1;
#pragma unroll
        for (int nt = 0; nt < 8; nt++) {
            ov[nt][0] *= cr0; ov[nt][1] *= cr0;
            ov[nt][2] *= cr1; ov[nt][3] *= cr1;
        }

        // ---- O += P V (bf16x3, P packed from registers, V^T via ldmatrix.trans)
        const int vrb = (lane & 7) + (((lane >> 3) & 1) << 3);
        const int vcb = (lane >> 4) << 3;
#pragma unroll
        for (int s = 0; s < 4; s++) {
            uint32_t pH[4], pL[4];
            split2(sv[2 * s][0],     sv[2 * s][1],     pH[0], pL[0]);
            split2(sv[2 * s][2],     sv[2 * s][3],     pH[1], pL[1]);
            split2(sv[2 * s + 1][0], sv[2 * s + 1][1], pH[2], pL[2]);
            split2(sv[2 * s + 1][2], sv[2 * s + 1][3], pH[3], pL[3]);
            const int vrow = s * 16 + vrb;
#pragma unroll
            for (int g = 0; g < 4; g++) {
                uint32_t vH4[4], vL4[4];
                uint32_t vo = sb + (vrow * APITCH + g * 16 + vcb) * 2;
                ldsm_x4t(vH4, vo + oVh);
                ldsm_x4t(vL4, vo + oVl);
                mma16816(ov[2 * g],     pH, vH4[0], vH4[1]);
                mma16816(ov[2 * g],     pH, vL4[0], vL4[1]);
                mma16816(ov[2 * g],     pL, vH4[0], vH4[1]);
                mma16816(ov[2 * g + 1], pH, vH4[2], vH4[3]);
                mma16816(ov[2 * g + 1], pH, vL4[2], vL4[3]);
                mma16816(ov[2 * g + 1], pL, vH4[2], vH4[3]);
            }
        }
    }

    // ---- finalize + write hi/lo ----
    const float inv0 = 1.0f / l_[0], inv1 = 1.0f / l_[1];
    const int gr0 = qb * 64 + wr + (lane >> 2);
    const int cb  = h * HD + (lane & 3) * 2;
#pragma unroll
    for (int nt = 0; nt < 8; nt++) {
        const int col = cb + nt * 8;
        uint32_t hi, lo;
        split2(ov[nt][0] * inv0, ov[nt][1] * inv0, hi, lo);
        *(uint32_t*)(Oh + (size_t)gr0 * DIM + col) = hi;
        *(uint32_t*)(Ol + (size_t)gr0 * DIM + col) = lo;
        split2(ov[nt][2] * inv1, ov[nt][3] * inv1, hi, lo);
        *(uint32_t*)(Oh + (size_t)(gr0 + 8) * DIM + col) = hi;
        *(uint32_t*)(Ol + (size_t)(gr0 + 8) * DIM + col) = lo;
    }
}

// ---------------- launch ----------------------------------------------------
extern "C" void kernel_launch(void* const* d_in, const int* in_sizes, int n_in,
                              void* d_out, int out_size)
{
    const int*   tokens = (const int*)  d_in[0];
    const float* emb    = (const float*)d_in[1];
    const float* pos    = (const float*)d_in[2];
    const float* mem    = (const float*)d_in[3];
    const float* ln1_s  = (const float*)d_in[4];
    const float* ln1_b  = (const float*)d_in[5];
    const float* wq     = (const float*)d_in[6];
    const float* wk     = (const float*)d_in[7];
    const float* wv     = (const float*)d_in[8];
    const float* wo     = (const float*)d_in[9];
    const float* ln2_s  = (const float*)d_in[10];
    const float* ln2_b  = (const float*)d_in[11];
    const float* w1     = (const float*)d_in[12];
    const float* b1     = (const float*)d_in[13];
    const float* w2     = (const float*)d_in[14];
    const float* b2     = (const float*)d_in[15];
    const float* lnm_s  = (const float*)d_in[16];
    const float* lnm_b  = (const float*)d_in[17];

    float *X;
    __nv_bfloat16 *Nh, *Nl, *QKVh, *QKVl, *Aoh, *Aol, *Fh, *Fl, *Wh, *Wl;
    cudaGetSymbolAddress((void**)&X,    g_X);
    cudaGetSymbolAddress((void**)&Nh,   g_Nh);
    cudaGetSymbolAddress((void**)&Nl,   g_Nl);
    cudaGetSymbolAddress((void**)&QKVh, g_QKVh);
    cudaGetSymbolAddress((void**)&QKVl, g_QKVl);
    cudaGetSymbolAddress((void**)&Aoh,  g_Ahp);
    cudaGetSymbolAddress((void**)&Aol,  g_Alp);
    cudaGetSymbolAddress((void**)&Fh,   g_Fh);
    cudaGetSymbolAddress((void**)&Fl,   g_Fl);
    cudaGetSymbolAddress((void**)&Wh,   g_Wh);
    cudaGetSymbolAddress((void**)&Wl,   g_Wl);

    cudaFuncSetAttribute(attn_tc, cudaFuncAttributeMaxDynamicSharedMemorySize, ATTN_SMEM);
    cudaFuncSetAttribute(gemm_tc<false, false, false, true >, cudaFuncAttributeMaxDynamicSharedMemorySize, GEMM_SMEM);
    cudaFuncSetAttribute(gemm_tc<false, true,  false, false>, cudaFuncAttributeMaxDynamicSharedMemorySize, GEMM_SMEM);
    cudaFuncSetAttribute(gemm_tc<true,  false, true,  true >, cudaFuncAttributeMaxDynamicSharedMemorySize, GEMM_SMEM);
    cudaFuncSetAttribute(gemm_tc<false, true,  true,  false>, cudaFuncAttributeMaxDynamicSharedMemorySize, GEMM_SMEM);

    // ---- weight pre-conversion ----
    {
        const int np = NLAYER * DIM * DIM / 4, nf = NLAYER * HID * DIM / 4;
        conv_hl_qkv<<<(np + 255) / 256, 256>>>(wq, Wh + OFF_QKV,           Wl + OFF_QKV);
        conv_hl_qkv<<<(np + 255) / 256, 256>>>(wk, Wh + OFF_QKV + DIM*DIM, Wl + OFF_QKV + DIM*DIM);
        conv_hl_qkv<<<(np + 255) / 256, 256>>>(wv, Wh + OFF_QKV + 2*DIM*DIM, Wl + OFF_QKV + 2*DIM*DIM);
        conv_hl_kernel<<<(np + 255) / 256, 256>>>(wo, Wh + OFF_WO, Wl + OFF_WO, np);
        conv_hl_kernel<<<(nf + 255) / 256, 256>>>(w1, Wh + OFF_W1, Wl + OFF_W1, nf);
        conv_hl_kernel<<<(nf + 255) / 256, 256>>>(w2, Wh + OFF_W2, Wl + OFF_W2, nf);
    }

    embed_kernel<<<(S_TOT * DIM + 255) / 256, 256>>>(tokens, emb, pos, mem, X);

    const dim3 gQKV(QKVN / 128, (S_TOT + 127) / 128);   // (18, 17)
    const dim3 gProj(DIM / 128, (S_TOT + 127) / 128);   // (6, 17)
    const dim3 gFF1 (HID / 128, (S_TOT + 127) / 128);   // (24, 17)

    for (int l = 0; l < NLAYER; l++) {
        ln_hl_kernel<<<S_TOT, 256>>>(X, ln1_s + l * DIM, ln1_b + l * DIM, Nh, Nl);

        gemm_tc<false, false, false, true><<<gQKV, 256, GEMM_SMEM>>>(
            Nh, Nl,
            Wh + OFF_QKV + (size_t)l * 3 * DIM * DIM, Wl + OFF_QKV + (size_t)l * 3 * DIM * DIM,
            nullptr, nullptr, nullptr, QKVh, QKVl, S_TOT, QKVN, DIM);

        attn_tc<<<dim3(S_TOT / 64, NHEAD), 128, ATTN_SMEM>>>(QKVh, QKVl, Aoh, Aol);

        gemm_tc<false, true, false, false><<<gProj, 256, GEMM_SMEM>>>(
            Aoh, Aol, Wh + OFF_WO + (size_t)l * DIM * DIM, Wl + OFF_WO + (size_t)l * DIM * DIM,
            nullptr, X, X, nullptr, nullptr, S_TOT, DIM, DIM);

        ln_hl_kernel<<<S_TOT, 256>>>(X, ln2_s + l * DIM, ln2_b + l * DIM, Nh, Nl);

        gemm_tc<true, false, true, true><<<gFF1, 256, GEMM_SMEM>>>(
            Nh, Nl, Wh + OFF_W1 + (size_t)l * HID * DIM, Wl + OFF_W1 + (size_t)l * HID * DIM,
            b1 + l * HID, nullptr, nullptr, Fh, Fl, S_TOT, HID, DIM);
        gemm_tc<false, true, true, false><<<gProj, 256, GEMM_SMEM>>>(
            Fh, Fl, Wh + OFF_W2 + (size_t)l * DIM * HID, Wl + OFF_W2 + (size_t)l * DIM * HID,
            b2 + l * DIM, X, X, nullptr, nullptr, S_TOT, DIM, HID);
    }

    ln_kernel<<<MEMN, 256>>>(X, lnm_s, lnm_b, (float*)d_out, S_TOT - MEMN);
}

// round 6
// speedup vs baseline: 3.5595x; 1.0051x over previous
#include <cuda_runtime.h>
#include <cuda_bf16.h>
#include <cstdint>

#define S_TOT 2112          // 64 mem + 2048 tokens
#define MEMN  64
#define DIM   768
#define HID   3072
#define NHEAD 12
#define HD    64
#define NLAYER 4
#define QKVN  (3 * DIM)     // 2304

// ---------------- scratch (device globals; no allocation allowed) ----------
__device__ __align__(16) float g_X [S_TOT * DIM];

__device__ __align__(16) __nv_bfloat16 g_Nh[S_TOT * DIM];
__device__ __align__(16) __nv_bfloat16 g_Nl[S_TOT * DIM];
__device__ __align__(16) __nv_bfloat16 g_QKVh[S_TOT * QKVN];
__device__ __align__(16) __nv_bfloat16 g_QKVl[S_TOT * QKVN];
__device__ __align__(16) __nv_bfloat16 g_Ahp[S_TOT * DIM];
__device__ __align__(16) __nv_bfloat16 g_Alp[S_TOT * DIM];
__device__ __align__(16) __nv_bfloat16 g_Fh[S_TOT * HID];
__device__ __align__(16) __nv_bfloat16 g_Fl[S_TOT * HID];

// preconverted weights (hi/lo bf16), all layers
#define WSZ_P   (NLAYER * DIM * DIM)
#define WSZ_FF  (NLAYER * HID * DIM)
#define OFF_QKV 0
#define OFF_WO  (OFF_QKV + 3 * WSZ_P)
#define OFF_W1  (OFF_WO + WSZ_P)
#define OFF_W2  (OFF_W1 + WSZ_FF)
#define WTOT    (OFF_W2 + WSZ_FF)
__device__ __align__(16) __nv_bfloat16 g_Wh[WTOT];
__device__ __align__(16) __nv_bfloat16 g_Wl[WTOT];

// =================== helpers ================================================
__device__ __forceinline__ uint32_t smem_u32(const void* p) {
    uint32_t a;
    asm("{ .reg .u64 t; cvta.to.shared.u64 t, %1; cvt.u32.u64 %0, t; }"
        : "=r"(a) : "l"(p));
    return a;
}
__device__ __forceinline__ void ldsm_x4(uint32_t* r, uint32_t addr) {
    asm volatile("ldmatrix.sync.aligned.m8n8.x4.shared.b16 {%0,%1,%2,%3}, [%4];"
                 : "=r"(r[0]), "=r"(r[1]), "=r"(r[2]), "=r"(r[3]) : "r"(addr));
}
__device__ __forceinline__ void ldsm_x4t(uint32_t* r, uint32_t addr) {
    asm volatile("ldmatrix.sync.aligned.m8n8.x4.trans.shared.b16 {%0,%1,%2,%3}, [%4];"
                 : "=r"(r[0]), "=r"(r[1]), "=r"(r[2]), "=r"(r[3]) : "r"(addr));
}
__device__ __forceinline__ void mma16816(float* c, const uint32_t* a,
                                         const uint32_t b0, const uint32_t b1) {
    asm volatile("mma.sync.aligned.m16n8k16.row.col.f32.bf16.bf16.f32 "
                 "{%0,%1,%2,%3}, {%4,%5,%6,%7}, {%8,%9}, {%0,%1,%2,%3};"
                 : "+f"(c[0]), "+f"(c[1]), "+f"(c[2]), "+f"(c[3])
                 : "r"(a[0]), "r"(a[1]), "r"(a[2]), "r"(a[3]), "r"(b0), "r"(b1));
}
__device__ __forceinline__ void cp_async16(uint32_t dst, const void* src, bool pred) {
    int sz = pred ? 16 : 0;
    asm volatile("cp.async.cg.shared.global [%0], [%1], 16, %2;"
                 :: "r"(dst), "l"(src), "r"(sz) : "memory");
}
#define CP_COMMIT() asm volatile("cp.async.commit_group;" ::: "memory")
#define CP_WAIT2()  asm volatile("cp.async.wait_group 2;" ::: "memory")
#define CP_WAIT1()  asm volatile("cp.async.wait_group 1;" ::: "memory")
#define CP_WAIT0()  asm volatile("cp.async.wait_group 0;" ::: "memory")

__device__ __forceinline__ void split4(float4 v, uint2& hi, uint2& lo)
{
    __nv_bfloat16 h0 = __float2bfloat16(v.x);
    __nv_bfloat16 h1 = __float2bfloat16(v.y);
    __nv_bfloat16 h2 = __float2bfloat16(v.z);
    __nv_bfloat16 h3 = __float2bfloat16(v.w);
    __nv_bfloat16 l0 = __float2bfloat16(v.x - __bfloat162float(h0));
    __nv_bfloat16 l1 = __float2bfloat16(v.y - __bfloat162float(h1));
    __nv_bfloat16 l2 = __float2bfloat16(v.z - __bfloat162float(h2));
    __nv_bfloat16 l3 = __float2bfloat16(v.w - __bfloat162float(h3));
    hi.x = (uint32_t)__bfloat16_as_ushort(h1) << 16 | __bfloat16_as_ushort(h0);
    hi.y = (uint32_t)__bfloat16_as_ushort(h3) << 16 | __bfloat16_as_ushort(h2);
    lo.x = (uint32_t)__bfloat16_as_ushort(l1) << 16 | __bfloat16_as_ushort(l0);
    lo.y = (uint32_t)__bfloat16_as_ushort(l3) << 16 | __bfloat16_as_ushort(l2);
}
__device__ __forceinline__ void split2(float a, float b, uint32_t& hi, uint32_t& lo)
{
    __nv_bfloat16 ha = __float2bfloat16(a), hb = __float2bfloat16(b);
    __nv_bfloat16 la = __float2bfloat16(a - __bfloat162float(ha));
    __nv_bfloat16 lb = __float2bfloat16(b - __bfloat162float(hb));
    hi = (uint32_t)__bfloat16_as_ushort(hb) << 16 | __bfloat16_as_ushort(ha);
    lo = (uint32_t)__bfloat16_as_ushort(lb) << 16 | __bfloat16_as_ushort(la);
}

// ---------------- weight pre-conversion (3 launches total) ------------------
// QKV: interleave wq/wk/wv per layer -> [L][3][DIM*DIM]
__global__ void conv_qkv_all(const float* __restrict__ wq,
                             const float* __restrict__ wk,
                             const float* __restrict__ wv,
                             __nv_bfloat16* __restrict__ dh,
                             __nv_bfloat16* __restrict__ dl)
{
    const int n4l = DIM * DIM / 4;
    const int per_t = NLAYER * n4l;
    int i = blockIdx.x * 256 + threadIdx.x;
    if (i >= 3 * per_t) return;
    int t = i / per_t;
    int r = i - t * per_t;
    int l = r / n4l, e = r - l * n4l;
    const float* s = (t == 0) ? wq : (t == 1) ? wk : wv;
    float4 v = ((const float4*)s)[(size_t)l * n4l + e];
    uint2 hi, lo;
    split4(v, hi, lo);
    size_t o = (size_t)l * (3 * n4l) + (size_t)t * n4l + e;
    ((uint2*)dh)[o] = hi;
    ((uint2*)dl)[o] = lo;
}
__global__ void conv_hl_kernel(const float* __restrict__ s,
                               __nv_bfloat16* __restrict__ dh,
                               __nv_bfloat16* __restrict__ dl, int n4)
{
    int i = blockIdx.x * 256 + threadIdx.x;
    if (i >= n4) return;
    float4 v = ((const float4*)s)[i];
    uint2 hi, lo;
    split4(v, hi, lo);
    ((uint2*)dh)[i] = hi;
    ((uint2*)dl)[i] = lo;
}
// FF: w1 then w2 into contiguous dst (dst = Wh+OFF_W1; OFF_W2 follows)
__global__ void conv_ff(const float* __restrict__ w1,
                        const float* __restrict__ w2,
                        __nv_bfloat16* __restrict__ dh,
                        __nv_bfloat16* __restrict__ dl)
{
    const int nf4 = WSZ_FF / 4;
    int i = blockIdx.x * 256 + threadIdx.x;
    if (i >= 2 * nf4) return;
    const float* s = (i < nf4) ? w1 : w2;
    int e = (i < nf4) ? i : i - nf4;
    float4 v = ((const float4*)s)[e];
    uint2 hi, lo;
    split4(v, hi, lo);
    ((uint2*)dh)[i] = hi;
    ((uint2*)dl)[i] = lo;
}

// ---------------- embedding ------------------------------------------------
__global__ void embed_kernel(const int* __restrict__ tokens,
                             const float* __restrict__ emb,
                             const float* __restrict__ pos,
                             const float* __restrict__ mem,
                             float* __restrict__ X)
{
    int idx = blockIdx.x * 256 + threadIdx.x;
    if (idx >= S_TOT * DIM) return;
    int s = idx / DIM;
    int d = idx - s * DIM;
    if (s < MEMN) {
        X[idx] = mem[s * DIM + d];
    } else {
        int t = s - MEMN;
        X[idx] = emb[tokens[t] * DIM + d] + pos[t * DIM + d];
    }
}

// ---------------- layernorm ------------------------------------------------
__device__ __forceinline__ void ln_stats(float v0, float v1, float v2,
                                         float& mean, float& inv)
{
    int t = threadIdx.x;
    float s = v0 + v1 + v2;
    float q = v0 * v0 + v1 * v1 + v2 * v2;
#pragma unroll
    for (int off = 16; off; off >>= 1) {
        s += __shfl_xor_sync(0xffffffffu, s, off);
        q += __shfl_xor_sync(0xffffffffu, q, off);
    }
    __shared__ float rs[8], rq[8];
    __shared__ float mean_sh, inv_sh;
    int w = t >> 5;
    if ((t & 31) == 0) { rs[w] = s; rq[w] = q; }
    __syncthreads();
    if (t == 0) {
        float S = 0.f, Q = 0.f;
#pragma unroll
        for (int i = 0; i < 8; i++) { S += rs[i]; Q += rq[i]; }
        float mn = S * (1.0f / DIM);
        float var = Q * (1.0f / DIM) - mn * mn;
        mean_sh = mn;
        inv_sh  = rsqrtf(var + 1e-5f);
    }
    __syncthreads();
    mean = mean_sh;
    inv  = inv_sh;
}

__global__ void ln_kernel(const float* __restrict__ X,
                          const float* __restrict__ g,
                          const float* __restrict__ bt,
                          float* __restrict__ out, int in_off)
{
    int row = blockIdx.x + in_off;
    const float* x = X + (size_t)row * DIM;
    int t = threadIdx.x;
    float v0 = x[t], v1 = x[t + 256], v2 = x[t + 512];
    float mean, inv;
    ln_stats(v0, v1, v2, mean, inv);
    float* o = out + (size_t)blockIdx.x * DIM;
    o[t]       = (v0 - mean) * inv * g[t]       + bt[t];
    o[t + 256] = (v1 - mean) * inv * g[t + 256] + bt[t + 256];
    o[t + 512] = (v2 - mean) * inv * g[t + 512] + bt[t + 512];
}

__global__ void ln_hl_kernel(const float* __restrict__ X,
                             const float* __restrict__ g,
                             const float* __restrict__ bt,
                             __nv_bfloat16* __restrict__ oh,
                             __nv_bfloat16* __restrict__ ol)
{
    int row = blockIdx.x;
    const float* x = X + (size_t)row * DIM;
    int t = threadIdx.x;
    float v0 = x[t], v1 = x[t + 256], v2 = x[t + 512];
    float mean, inv;
    ln_stats(v0, v1, v2, mean, inv);
    size_t base = (size_t)row * DIM;
#pragma unroll
    for (int i = 0; i < 3; i++) {
        int c = t + i * 256;
        float v = (i == 0) ? v0 : (i == 1) ? v1 : v2;
        float y = (v - mean) * inv * g[c] + bt[c];
        __nv_bfloat16 h = __float2bfloat16(y);
        oh[base + c] = h;
        ol[base + c] = __float2bfloat16(y - __bfloat162float(h));
    }
}

__device__ __forceinline__ float gelu_tanh(float x)
{
    const float c = 0.7978845608028654f;
    float u = c * (x + 0.044715f * x * x * x);
    return 0.5f * x * (1.0f + tanhf(u));
}

// =================== bf16x3 tensor-core GEMM (pipelined) ====================
#define GPITCH 40
#define GMATB  10240
#define GSTAGEB (4 * GMATB)
#define NSTAGE 4
#define GEMM_SMEM (NSTAGE * GSTAGEB)

template <bool GELU, bool RES, bool BIAS, bool OUTHL>
__global__ __launch_bounds__(256, 1)
void gemm_tc(const __nv_bfloat16* __restrict__ Ah, const __nv_bfloat16* __restrict__ Al,
             const __nv_bfloat16* __restrict__ Bh, const __nv_bfloat16* __restrict__ Bl,
             const float* __restrict__ bias, const float* __restrict__ resid,
             float* __restrict__ C,
             __nv_bfloat16* __restrict__ Oh, __nv_bfloat16* __restrict__ Ol,
             int Mr, int N, int K)
{
    extern __shared__ char smem[];
    const uint32_t sb = smem_u32(smem);
    const int tid = threadIdx.x, wid = tid >> 5, lane = tid & 31;
    const int bm = blockIdx.y, bn = blockIdx.x;
    const int wm = (wid >> 2) * 64;
    const int wn = (wid & 3) * 32;

    const int lrow = tid >> 2;
    const int kc   = tid & 3;
    const int KT = K >> 5;

    float acc[4][4][4];
#pragma unroll
    for (int i = 0; i < 4; i++)
#pragma unroll
        for (int j = 0; j < 4; j++)
#pragma unroll
            for (int k = 0; k < 4; k++) acc[i][j][k] = 0.f;

    auto issue = [&](int kt) {
        const uint32_t stg = sb + (kt % NSTAGE) * GSTAGEB;
        const int kb = kt * 32;
#pragma unroll
        for (int half = 0; half < 2; half++) {
            const int row = lrow + half * 64;
            const uint32_t d = stg + row * (GPITCH * 2) + kc * 16;
            int ga = bm * 128 + row;
            const bool av = ga < Mr;
            if (!av) ga = 0;
            const size_t aoff = (size_t)ga * K + kb + kc * 8;
            const size_t boff = (size_t)(bn * 128 + row) * K + kb + kc * 8;
            cp_async16(d,             Ah + aoff, av);
            cp_async16(d + GMATB,     Al + aoff, av);
            cp_async16(d + 2 * GMATB, Bh + boff, true);
            cp_async16(d + 3 * GMATB, Bl + boff, true);
        }
    };

#pragma unroll
    for (int p = 0; p < NSTAGE - 1; p++) { issue(p); CP_COMMIT(); }

    const int arow = wm + (lane & 15);
    const int acO  = (lane >> 4) << 3;
    const int brow = wn + (lane & 7) + ((lane >> 4) << 3);
    const int bcO  = ((lane >> 3) & 1) << 3;

    for (int kt = 0; kt < KT; kt++) {
        CP_WAIT2();
        __syncthreads();
        if (kt + NSTAGE - 1 < KT) { issue(kt + NSTAGE - 1); CP_COMMIT(); }

        const uint32_t base = sb + (kt % NSTAGE) * GSTAGEB;

        // ---- load ALL fragments for both k-halves up front (overlap LDS w/ MMA)
        uint32_t aH[2][4][4], aL[2][4][4], bH[2][2][4], bL[2][2][4];
#pragma unroll
        for (int ks = 0; ks < 2; ks++) {
            const int k0 = ks * 16;
#pragma unroll
            for (int mt = 0; mt < 4; mt++) {
                uint32_t ad = base + ((arow + mt * 16) * GPITCH + k0 + acO) * 2;
                ldsm_x4(aH[ks][mt], ad);
                ldsm_x4(aL[ks][mt], ad + GMATB);
            }
#pragma unroll
            for (int n2 = 0; n2 < 2; n2++) {
                uint32_t bd = base + 2 * GMATB + ((brow + n2 * 16) * GPITCH + k0 + bcO) * 2;
                ldsm_x4(bH[ks][n2], bd);
                ldsm_x4(bL[ks][n2], bd + GMATB);
            }
        }
#pragma unroll
        for (int ks = 0; ks < 2; ks++)
#pragma unroll
            for (int mt = 0; mt < 4; mt++)
#pragma unroll
                for (int nt = 0; nt < 4; nt++) {
                    const int n2 = nt >> 1, hb = (nt & 1) * 2;
                    mma16816(acc[mt][nt], aH[ks][mt], bH[ks][n2][hb], bH[ks][n2][hb + 1]);
                    mma16816(acc[mt][nt], aH[ks][mt], bL[ks][n2][hb], bL[ks][n2][hb + 1]);
                    mma16816(acc[mt][nt], aL[ks][mt], bH[ks][n2][hb], bH[ks][n2][hb + 1]);
                }
    }

#pragma unroll
    for (int mt = 0; mt < 4; mt++) {
        const int r0 = bm * 128 + wm + mt * 16 + (lane >> 2);
#pragma unroll
        for (int nt = 0; nt < 4; nt++) {
            const int col = bn * 128 + wn + nt * 8 + (lane & 3) * 2;
            float* c = acc[mt][nt];
            float bx = 0.f, by = 0.f;
            if (BIAS) { float2 bv = *(const float2*)(bias + col); bx = bv.x; by = bv.y; }
#pragma unroll
            for (int hh = 0; hh < 2; hh++) {
                const int r = r0 + hh * 8;
                if (r >= Mr) continue;
                float v0 = c[hh * 2 + 0], v1 = c[hh * 2 + 1];
                if (BIAS) { v0 += bx; v1 += by; }
                if (GELU) { v0 = gelu_tanh(v0); v1 = gelu_tanh(v1); }
                if (OUTHL) {
                    uint32_t hi, lo;
                    split2(v0, v1, hi, lo);
                    *(uint32_t*)(Oh + (size_t)r * N + col) = hi;
                    *(uint32_t*)(Ol + (size_t)r * N + col) = lo;
                } else {
                    if (RES) {
                        float2 rv = *(const float2*)(resid + (size_t)r * N + col);
                        v0 += rv.x; v1 += rv.y;
                    }
                    *(float2*)(C + (size_t)r * N + col) = make_float2(v0, v1);
                }
            }
        }
    }
}

// =================== tensor-core flash attention (2-stage KV pipeline) ======
// 4 warps / block; block = (qb: 64 queries, h: head). bf16x3 QK and PV.
// smem: Qh Ql (2 mats) + 2 KV stages x {Kh Kl Vh Vl} (8 mats) = 10 x 9216 B.
#define APITCH 72
#define AMATB  9216
#define ATTN_SMEM (10 * AMATB)

__global__ __launch_bounds__(128)
void attn_tc(const __nv_bfloat16* __restrict__ QKVh,
             const __nv_bfloat16* __restrict__ QKVl,
             __nv_bfloat16* __restrict__ Oh, __nv_bfloat16* __restrict__ Ol)
{
    extern __shared__ char asmem[];
    const uint32_t sb = smem_u32(asmem);
    const uint32_t oQh = 0, oQl = AMATB;
    const int qb = blockIdx.x, h = blockIdx.y;
    const int tid = threadIdx.x, wid = tid >> 5, lane = tid & 31;
    const int wr = wid * 16;

    // load Q hi/lo (group 0)
#pragma unroll
    for (int i = 0; i < 4; i++) {
        int idx = tid + i * 128;
        int row = idx >> 3, ch = idx & 7;
        size_t goff = (size_t)(qb * 64 + row) * QKVN + h * HD + ch * 8;
        uint32_t soff = row * (APITCH * 2) + ch * 16;
        cp_async16(sb + oQh + soff, QKVh + goff, true);
        cp_async16(sb + oQl + soff, QKVl + goff, true);
    }
    CP_COMMIT();

    auto issueKV = [&](int kb) {
        const uint32_t st = sb + 2 * AMATB + (kb & 1) * (4 * AMATB);
#pragma unroll
        for (int i = 0; i < 4; i++) {
            int idx = tid + i * 128;
            int row = idx >> 3, ch = idx & 7;
            size_t gK = (size_t)(kb * 64 + row) * QKVN + DIM + h * HD + ch * 8;
            size_t gV = (size_t)(kb * 64 + row) * QKVN + 2 * DIM + h * HD + ch * 8;
            uint32_t soff = row * (APITCH * 2) + ch * 16;
            cp_async16(st + soff,             QKVh + gK, true);
            cp_async16(st + AMATB + soff,     QKVl + gK, true);
            cp_async16(st + 2 * AMATB + soff, QKVh + gV, true);
            cp_async16(st + 3 * AMATB + soff, QKVl + gV, true);
        }
        CP_COMMIT();
    };

    issueKV(0);
    if (qb >= 1) issueKV(1);

    float m_[2] = {-1e30f, -1e30f}, l_[2] = {0.f, 0.f};
    float ov[8][4];
#pragma unroll
    for (int i = 0; i < 8; i++)
#pragma unroll
        for (int j = 0; j < 4; j++) ov[i][j] = 0.f;
    const float scale = 0.125f;

    const int ar = wr + (lane & 15);
    const int ac = (lane >> 4) << 3;
    const int br = (lane & 7) + ((lane >> 4) << 3);
    const int bc = ((lane >> 3) & 1) << 3;
    const int vrb = (lane & 7) + (((lane >> 3) & 1) << 3);
    const int vcb = (lane >> 4) << 3;
    const int lr0 = lane >> 2;
    const int lc0 = (lane & 3) * 2;

    for (int kb = 0; kb <= qb; kb++) {
        if (kb + 1 <= qb) { CP_WAIT1(); } else { CP_WAIT0(); }
        __syncthreads();

        const uint32_t st  = sb + 2 * AMATB + (kb & 1) * (4 * AMATB);
        const uint32_t oKh = st, oKl = st + AMATB;
        const uint32_t oVh = st + 2 * AMATB, oVl = st + 3 * AMATB;

        // ---- S = Q K^T (bf16x3) ----
        float sv[8][4];
#pragma unroll
        for (int i = 0; i < 8; i++)
#pragma unroll
            for (int j = 0; j < 4; j++) sv[i][j] = 0.f;

#pragma unroll
        for (int ks = 0; ks < 4; ks++) {
            uint32_t aH[4], aL[4];
            uint32_t ao = sb + (ar * APITCH + ks * 16 + ac) * 2;
            ldsm_x4(aH, ao + oQh);
            ldsm_x4(aL, ao + oQl);
#pragma unroll
            for (int g = 0; g < 4; g++) {
                uint32_t bH4[4], bL4[4];
                uint32_t bo = ((g * 16 + br) * APITCH + ks * 16 + bc) * 2;
                ldsm_x4(bH4, bo + oKh);
                ldsm_x4(bL4, bo + oKl);
                mma16816(sv[2 * g],     aH, bH4[0], bH4[1]);
                mma16816(sv[2 * g],     aH, bL4[0], bL4[1]);
                mma16816(sv[2 * g],     aL, bH4[0], bH4[1]);
                mma16816(sv[2 * g + 1], aH, bH4[2], bH4[3]);
                mma16816(sv[2 * g + 1], aH, bL4[2], bL4[3]);
                mma16816(sv[2 * g + 1], aL, bH4[2], bH4[3]);
            }
        }

        // ---- scale + causal mask ----
#pragma unroll
        for (int nt = 0; nt < 8; nt++)
#pragma unroll
            for (int e = 0; e < 4; e++) {
                float x = sv[nt][e] * scale;
                if (kb == qb) {
                    int kcol = nt * 8 + lc0 + (e & 1);
                    int qrow = wr + lr0 + ((e >> 1) << 3);
                    if (kcol > qrow) x = -1e30f;
                }
                sv[nt][e] = x;
            }

        // ---- online softmax ----
        float mx0 = -1e30f, mx1 = -1e30f;
#pragma unroll
        for (int nt = 0; nt < 8; nt++) {
            mx0 = fmaxf(mx0, fmaxf(sv[nt][0], sv[nt][1]));
            mx1 = fmaxf(mx1, fmaxf(sv[nt][2], sv[nt][3]));
        }
        mx0 = fmaxf(mx0, __shfl_xor_sync(0xffffffffu, mx0, 1));
        mx0 = fmaxf(mx0, __shfl_xor_sync(0xffffffffu, mx0, 2));
        mx1 = fmaxf(mx1, __shfl_xor_sync(0xffffffffu, mx1, 1));
        mx1 = fmaxf(mx1, __shfl_xor_sync(0xffffffffu, mx1, 2));
        float mn0 = fmaxf(m_[0], mx0), mn1 = fmaxf(m_[1], mx1);
        float cr0 = __expf(m_[0] - mn0), cr1 = __expf(m_[1] - mn1);
        float sum0 = 0.f, sum1 = 0.f;
#pragma unroll
        for (int nt = 0; nt < 8; nt++) {
            float p0 = __expf(sv[nt][0] - mn0);
            float p1 = __expf(sv[nt][1] - mn0);
            float p2 = __expf(sv[nt][2] - mn1);
            float p3 = __expf(sv[nt][3] - mn1);
            sv[nt][0] = p0; sv[nt][1] = p1; sv[nt][2] = p2; sv[nt][3] = p3;
            sum0 += p0 + p1;
            sum1 += p2 + p3;
        }
        sum0 += __shfl_xor_sync(0xffffffffu, sum0, 1);
        sum0 += __shfl_xor_sync(0xffffffffu, sum0, 2);
        sum1 += __shfl_xor_sync(0xffffffffu, sum1, 1);
        sum1 += __shfl_xor_sync(0xffffffffu, sum1, 2);
        l_[0] = l_[0] * cr0 + sum0;
        l_[1] = l_[1] * cr1 + sum1;
        m_[0] = mn0; m_[1] = mn1;
#pragma unroll
        for (int nt = 0; nt < 8; nt++) {
            ov[nt][0] *= cr0; ov[nt][1] *= cr0;
            ov[nt][2] *= cr1; ov[nt][3] *= cr1;
        }

        // ---- O += P V (bf16x3) ----
#pragma unroll
        for (int s = 0; s < 4; s++) {
            uint32_t pH[4], pL[4];
            split2(sv[2 * s][0],     sv[2 * s][1],     pH[0], pL[0]);
            split2(sv[2 * s][2],     sv[2 * s][3],     pH[1], pL[1]);
            split2(sv[2 * s + 1][0], sv[2 * s + 1][1], pH[2], pL[2]);
            split2(sv[2 * s + 1][2], sv[2 * s + 1][3], pH[3], pL[3]);
            const int vrow = s * 16 + vrb;
#pragma unroll
            for (int g = 0; g < 4; g++) {
                uint32_t vH4[4], vL4[4];
                uint32_t vo = (vrow * APITCH + g * 16 + vcb) * 2;
                ldsm_x4t(vH4, vo + oVh);
                ldsm_x4t(vL4, vo + oVl);
                mma16816(ov[2 * g],     pH, vH4[0], vH4[1]);
                mma16816(ov[2 * g],     pH, vL4[0], vL4[1]);
                mma16816(ov[2 * g],     pL, vH4[0], vH4[1]);
                mma16816(ov[2 * g + 1], pH, vH4[2], vH4[3]);
                mma16816(ov[2 * g + 1], pH, vL4[2], vL4[3]);
                mma16816(ov[2 * g + 1], pL, vH4[2], vH4[3]);
            }
        }

        __syncthreads();                 // compute done before refilling this buffer
        if (kb + 2 <= qb) issueKV(kb + 2);
    }

    // ---- finalize + write hi/lo ----
    const float inv0 = 1.0f / l_[0], inv1 = 1.0f / l_[1];
    const int gr0 = qb * 64 + wr + (lane >> 2);
    const int cb  = h * HD + (lane & 3) * 2;
#pragma unroll
    for (int nt = 0; nt < 8; nt++) {
        const int col = cb + nt * 8;
        uint32_t hi, lo;
        split2(ov[nt][0] * inv0, ov[nt][1] * inv0, hi, lo);
        *(uint32_t*)(Oh + (size_t)gr0 * DIM + col) = hi;
        *(uint32_t*)(Ol + (size_t)gr0 * DIM + col) = lo;
        split2(ov[nt][2] * inv1, ov[nt][3] * inv1, hi, lo);
        *(uint32_t*)(Oh + (size_t)(gr0 + 8) * DIM + col) = hi;
        *(uint32_t*)(Ol + (size_t)(gr0 + 8) * DIM + col) = lo;
    }
}

// ---------------- launch ----------------------------------------------------
extern "C" void kernel_launch(void* const* d_in, const int* in_sizes, int n_in,
                              void* d_out, int out_size)
{
    const int*   tokens = (const int*)  d_in[0];
    const float* emb    = (const float*)d_in[1];
    const float* pos    = (const float*)d_in[2];
    const float* mem    = (const float*)d_in[3];
    const float* ln1_s  = (const float*)d_in[4];
    const float* ln1_b  = (const float*)d_in[5];
    const float* wq     = (const float*)d_in[6];
    const float* wk     = (const float*)d_in[7];
    const float* wv     = (const float*)d_in[8];
    const float* wo     = (const float*)d_in[9];
    const float* ln2_s  = (const float*)d_in[10];
    const float* ln2_b  = (const float*)d_in[11];
    const float* w1     = (const float*)d_in[12];
    const float* b1     = (const float*)d_in[13];
    const float* w2     = (const float*)d_in[14];
    const float* b2     = (const float*)d_in[15];
    const float* lnm_s  = (const float*)d_in[16];
    const float* lnm_b  = (const float*)d_in[17];

    float *X;
    __nv_bfloat16 *Nh, *Nl, *QKVh, *QKVl, *Aoh, *Aol, *Fh, *Fl, *Wh, *Wl;
    cudaGetSymbolAddress((void**)&X,    g_X);
    cudaGetSymbolAddress((void**)&Nh,   g_Nh);
    cudaGetSymbolAddress((void**)&Nl,   g_Nl);
    cudaGetSymbolAddress((void**)&QKVh, g_QKVh);
    cudaGetSymbolAddress((void**)&QKVl, g_QKVl);
    cudaGetSymbolAddress((void**)&Aoh,  g_Ahp);
    cudaGetSymbolAddress((void**)&Aol,  g_Alp);
    cudaGetSymbolAddress((void**)&Fh,   g_Fh);
    cudaGetSymbolAddress((void**)&Fl,   g_Fl);
    cudaGetSymbolAddress((void**)&Wh,   g_Wh);
    cudaGetSymbolAddress((void**)&Wl,   g_Wl);

    cudaFuncSetAttribute(attn_tc, cudaFuncAttributeMaxDynamicSharedMemorySize, ATTN_SMEM);
    cudaFuncSetAttribute(gemm_tc<false, false, false, true >, cudaFuncAttributeMaxDynamicSharedMemorySize, GEMM_SMEM);
    cudaFuncSetAttribute(gemm_tc<false, true,  false, false>, cudaFuncAttributeMaxDynamicSharedMemorySize, GEMM_SMEM);
    cudaFuncSetAttribute(gemm_tc<true,  false, true,  true >, cudaFuncAttributeMaxDynamicSharedMemorySize, GEMM_SMEM);
    cudaFuncSetAttribute(gemm_tc<false, true,  true,  false>, cudaFuncAttributeMaxDynamicSharedMemorySize, GEMM_SMEM);

    // ---- weight pre-conversion (3 launches) ----
    {
        const int nqkv = 3 * WSZ_P / 4;
        const int np   = WSZ_P / 4;
        const int nff  = 2 * WSZ_FF / 4;
        conv_qkv_all<<<(nqkv + 255) / 256, 256>>>(wq, wk, wv, Wh + OFF_QKV, Wl + OFF_QKV);
        conv_hl_kernel<<<(np + 255) / 256, 256>>>(wo, Wh + OFF_WO, Wl + OFF_WO, np);
        conv_ff<<<(nff + 255) / 256, 256>>>(w1, w2, Wh + OFF_W1, Wl + OFF_W1);
    }

    embed_kernel<<<(S_TOT * DIM + 255) / 256, 256>>>(tokens, emb, pos, mem, X);

    const dim3 gQKV(QKVN / 128, (S_TOT + 127) / 128);   // (18, 17)
    const dim3 gProj(DIM / 128, (S_TOT + 127) / 128);   // (6, 17)
    const dim3 gFF1 (HID / 128, (S_TOT + 127) / 128);   // (24, 17)

    for (int l = 0; l < NLAYER; l++) {
        ln_hl_kernel<<<S_TOT, 256>>>(X, ln1_s + l * DIM, ln1_b + l * DIM, Nh, Nl);

        gemm_tc<false, false, false, true><<<gQKV, 256, GEMM_SMEM>>>(
            Nh, Nl,
            Wh + OFF_QKV + (size_t)l * 3 * DIM * DIM, Wl + OFF_QKV + (size_t)l * 3 * DIM * DIM,
            nullptr, nullptr, nullptr, QKVh, QKVl, S_TOT, QKVN, DIM);

        attn_tc<<<dim3(S_TOT / 64, NHEAD), 128, ATTN_SMEM>>>(QKVh, QKVl, Aoh, Aol);

        gemm_tc<false, true, false, false><<<gProj, 256, GEMM_SMEM>>>(
            Aoh, Aol, Wh + OFF_WO + (size_t)l * DIM * DIM, Wl + OFF_WO + (size_t)l * DIM * DIM,
            nullptr, X, X, nullptr, nullptr, S_TOT, DIM, DIM);

        ln_hl_kernel<<<S_TOT, 256>>>(X, ln2_s + l * DIM, ln2_b + l * DIM, Nh, Nl);

        gemm_tc<true, false, true, true><<<gFF1, 256, GEMM_SMEM>>>(
            Nh, Nl, Wh + OFF_W1 + (size_t)l * HID * DIM, Wl + OFF_W1 + (size_t)l * HID * DIM,
            b1 + l * HID, nullptr, nullptr, Fh, Fl, S_TOT, HID, DIM);
        gemm_tc<false, true, true, false><<<gProj, 256, GEMM_SMEM>>>(
            Fh, Fl, Wh + OFF_W2 + (size_t)l * DIM * HID, Wl + OFF_W2 + (size_t)l * DIM * HID,
            b2 + l * DIM, X, X, nullptr, nullptr, S_TOT, DIM, HID);
    }

    ln_kernel<<<MEMN, 256>>>(X, lnm_s, lnm_b, (float*)d_out, S_TOT - MEMN);
}